// round 12
// baseline (speedup 1.0000x reference)
#include <cuda_runtime.h>
#include <cuda_bf16.h>
#include <cuda_fp16.h>
#include <math.h>

// ---------------- Problem constants ----------------
#define BATCH   128
#define CIN     256
#define HIN     8
#define WIN     32
#define RH      16
#define RW      64
#define HF      8
#define WF      32
#define LPOS    256
#define XOH     32
#define YOH     8
#define CENC    296
#define HID     256
#define NC      163
#define TLEN    32

#define PADH    18
#define PADW    66

// ---------------- Scratch ----------------
__device__ float    g_resT[BATCH*PADH*PADW*CIN];
__device__ unsigned g_wrb [9*128*256];
__device__ float    g_wc  [768*NC];
__device__ float    g_bc  [768];
__device__ float    g_enc[BATCH*LPOS*CENC];
__device__ unsigned g_preh[BATCH*LPOS*128];
__device__ float    g_giw[TLEN*768*BATCH];
__device__ float    g_hT   [HID*BATCH];
__device__ float    g_hcatT[1280*BATCH];
__device__ float    g_ctxT [CENC*BATCH];
__device__ float    g_nll  [TLEN*BATCH];
__device__ unsigned g_bar_arrive;
__device__ unsigned g_bar_epoch;

// ---------------- helpers ----------------
__device__ __forceinline__ float warp_sum(float v){
    #pragma unroll
    for (int o = 16; o; o >>= 1) v += __shfl_down_sync(0xffffffffu, v, o);
    return v;
}
__device__ __forceinline__ float tf32r(float f){
    unsigned u; asm("cvt.rna.tf32.f32 %0, %1;" : "=r"(u) : "f"(f));
    return __uint_as_float(u);
}
__device__ __forceinline__ unsigned pkbf(float a, float b){
    __nv_bfloat162 h = __floats2bfloat162_rn(a, b);
    return *(unsigned*)&h;
}
__device__ __forceinline__ unsigned pkhf(float a, float b){
    __half2 h = __floats2half2_rn(a, b);
    return *(unsigned*)&h;
}
__device__ __forceinline__ unsigned hadd2u(unsigned a, unsigned b){
    unsigned r; asm("add.f16x2 %0, %1, %2;" : "=r"(r) : "r"(a), "r"(b)); return r;
}
__device__ __forceinline__ unsigned tanh2u(unsigned a){
    unsigned r; asm("tanh.approx.f16x2 %0, %1;" : "=r"(r) : "r"(a)); return r;
}
__device__ __forceinline__ float2 uph(unsigned u){
    return __half22float2(*(__half2*)&u);
}
__device__ __forceinline__ void mma_tf32(float* c, const unsigned* a, unsigned b0, unsigned b1){
    asm volatile("mma.sync.aligned.m16n8k8.row.col.f32.tf32.tf32.f32 "
        "{%0,%1,%2,%3}, {%4,%5,%6,%7}, {%8,%9}, {%0,%1,%2,%3};"
        : "+f"(c[0]), "+f"(c[1]), "+f"(c[2]), "+f"(c[3])
        : "r"(a[0]), "r"(a[1]), "r"(a[2]), "r"(a[3]), "r"(b0), "r"(b1));
}
__device__ __forceinline__ void mma_bf16(float* c, const unsigned* a, unsigned b0, unsigned b1){
    asm volatile("mma.sync.aligned.m16n8k16.row.col.f32.bf16.bf16.f32 "
        "{%0,%1,%2,%3}, {%4,%5,%6,%7}, {%8,%9}, {%0,%1,%2,%3};"
        : "+f"(c[0]), "+f"(c[1]), "+f"(c[2]), "+f"(c[3])
        : "r"(a[0]), "r"(a[1]), "r"(a[2]), "r"(a[3]), "r"(b0), "r"(b1));
}
__device__ __forceinline__ unsigned ld_acq(unsigned* p){
    unsigned v; asm volatile("ld.acquire.gpu.u32 %0, [%1];" : "=r"(v) : "l"(p)); return v;
}
__device__ __forceinline__ void grid_barrier(unsigned target){
    __syncthreads();
    if (threadIdx.x == 0){
        unsigned t;
        asm volatile("atom.acq_rel.gpu.global.add.u32 %0, [%1], 1;"
                     : "=r"(t) : "l"(&g_bar_arrive) : "memory");
        if (t == gridDim.x - 1){
            g_bar_arrive = 0u;
            asm volatile("red.release.gpu.global.add.u32 [%0], 1;" :: "l"(&g_bar_epoch) : "memory");
        } else {
            while ((int)(ld_acq(&g_bar_epoch) - target) < 0) __nanosleep(64);
        }
    }
    __syncthreads();
}

// ---------------- K1: fused prep ----------------
#define RES_BLKS  (8*PADH*BATCH)
#define WRB_BLKS  ((9*128*256)/256)
#define WC_BLKS   (768/4)
__global__ __launch_bounds__(256) void prep_kernel(
    const float* __restrict__ x, const float* __restrict__ conv_w,
    const float* __restrict__ wih, const float* __restrict__ bih,
    const float* __restrict__ word_w, const float* __restrict__ word_b)
{
    __shared__ float smem_u[32*67];
    int bid = blockIdx.x;
    int t = threadIdx.x;
    if (bid < RES_BLKS){
        float (*tile)[67] = (float(*)[67])smem_u;
        int cg = bid % 8;
        int yp = (bid / 8) % PADH;
        int b  = bid / (8*PADH);
        int xo  = t & 63;
        int cl0 = (t >> 6)*8;
        bool interior = (yp >= 1 && yp <= 16);
        int y0c = 0, y1c = 0; float fy = 0.f;
        if (interior){
            float sy = 0.5f*(yp-1) - 0.25f;
            int y0 = (int)floorf(sy); fy = sy - (float)y0;
            y0c = y0 < 0 ? 0 : y0;
            y1c = (y0+1) > (HIN-1) ? (HIN-1) : (y0+1);
        }
        float sx = 0.5f*xo - 0.25f;
        int x0 = (int)floorf(sx); float fx = sx - (float)x0;
        int x0c = x0 < 0 ? 0 : x0;
        int x1c = (x0+1) > (WIN-1) ? (WIN-1) : (x0+1);
        #pragma unroll
        for (int i = 0; i < 8; i++){
            int cl = cl0 + i;
            float v = 0.f;
            if (interior){
                const float* base = x + (size_t)(b*CIN + cg*32 + cl)*(HIN*WIN);
                float v00 = base[y0c*WIN + x0c], v01 = base[y0c*WIN + x1c];
                float v10 = base[y1c*WIN + x0c], v11 = base[y1c*WIN + x1c];
                v = (1.f-fy)*((1.f-fx)*v00 + fx*v01) + fy*((1.f-fx)*v10 + fx*v11);
            }
            tile[cl][xo+1] = v;
        }
        if (t < 32){ tile[t][0] = 0.f; tile[t][65] = 0.f; }
        __syncthreads();
        int warp = t >> 5, lane = t & 31;
        for (int xp = warp; xp < PADW; xp += 8){
            g_resT[(((size_t)b*PADH + yp)*PADW + xp)*CIN + cg*32 + lane] = tile[lane][xp];
        }
    } else if (bid < RES_BLKS + WRB_BLKS){
        int idx = (bid - RES_BLKS)*256 + t;
        int o  = idx & 255;
        int kp = (idx >> 8) & 127;
        int s  = idx >> 15;
        float f0 = conv_w[((size_t)o*CIN + 2*kp  )*9 + s];
        float f1 = conv_w[((size_t)o*CIN + 2*kp+1)*9 + s];
        g_wrb[idx] = pkbf(f0, f1);
    } else {
        int j0 = (bid - RES_BLKS - WRB_BLKS)*4;
        float* s_wih = smem_u;
        for (int idx = t; idx < 1024; idx += 256){
            int r = idx >> 8, k = idx & 255;
            s_wih[idx] = wih[(size_t)(j0+r)*552 + k];
        }
        __syncthreads();
        if (t < NC){
            float a0=0.f, a1=0.f, a2=0.f, a3=0.f;
            for (int k = 0; k < 256; k++){
                float wv = word_w[k*NC + t];
                a0 += s_wih[      k]*wv;
                a1 += s_wih[256 + k]*wv;
                a2 += s_wih[512 + k]*wv;
                a3 += s_wih[768 + k]*wv;
            }
            g_wc[(size_t)(j0+0)*NC + t] = a0;
            g_wc[(size_t)(j0+1)*NC + t] = a1;
            g_wc[(size_t)(j0+2)*NC + t] = a2;
            g_wc[(size_t)(j0+3)*NC + t] = a3;
        }
        if (t < 4){
            float s = bih[j0 + t];
            for (int k = 0; k < 256; k++) s += s_wih[t*256 + k]*word_b[k];
            g_bc[j0 + t] = s;
        }
    }
}

// ---------------- K2: conv3x3 bf16 MMA, double-buffered B ----------------
#define ASTR 12
#define BSTR 12
#define AS_U (4*66*ASTR)          // 3168
#define BS2_U (2*64*BSTR)         // 1536 per group (double buffer)
#define SMU_SZ (AS_U + 4*BS2_U)   // 9312 u32 >= epilogue 8704 floats
__global__ __launch_bounds__(512, 1) void conv_mma_kernel(const float* __restrict__ conv_b,
                                                          const float* __restrict__ x_emb,
                                                          const float* __restrict__ y_emb){
    __shared__ __align__(16) unsigned smu[SMU_SZ];
    unsigned* As = smu;
    unsigned* Bs = smu + AS_U;
    int b = blockIdx.x, ytile = blockIdx.y;
    int y0 = ytile*2;
    int tid = threadIdx.x;
    int w = tid >> 5, lane = tid & 31;
    int wm = w & 3, g = w >> 2;
    int quad = lane >> 2, qk = lane & 3;
    int gtid = tid & 127;
    unsigned* BgBuf = Bs + g*BS2_U;
    int yy = wm >> 1;
    int x0 = (wm & 1) << 5;
    int kp2 = gtid >> 6, oo = gtid & 63;

    float acc[2][8][4];
    #pragma unroll
    for (int i=0;i<2;i++)
        #pragma unroll
        for (int j=0;j<8;j++){ acc[i][j][0]=0.f; acc[i][j][1]=0.f; acc[i][j][2]=0.f; acc[i][j][3]=0.f; }

    const float* srcA = g_resT + (size_t)(b*PADH + y0) * (PADW*CIN);
    for (int chunk = 0; chunk < 16; chunk++){
        int c0 = chunk*16;
        __syncthreads();
        for (int e4 = tid; e4 < 4*66*4; e4 += 512){
            int c4 = e4 & 3;
            int xr = (e4 >> 2) % 66;
            int r  = e4 / 264;
            float4 v = *(const float4*)(srcA + ((size_t)r*PADW + xr)*CIN + c0 + c4*4);
            unsigned* d = As + (r*66 + xr)*ASTR + c4*2;
            d[0] = pkbf(v.x, v.y);
            d[1] = pkbf(v.z, v.w);
        }
        __syncthreads();
        // pre-stage B for s=0
        {
            const unsigned* src = g_wrb + ((size_t)(0*128 + chunk*8))*256 + g*64 + oo;
            unsigned* dst = BgBuf;
            #pragma unroll
            for (int kq = 0; kq < 4; kq++){
                int kp = kp2 + kq*2;
                dst[oo*BSTR + kp] = src[(size_t)kp*256];
            }
        }
        asm volatile("bar.sync %0, 128;" :: "r"(g+1));
        for (int s = 0; s < 9; s++){
            // prefetch next shift's B into other buffer (overlaps MMA)
            if (s < 8){
                const unsigned* src = g_wrb + ((size_t)((s+1)*128 + chunk*8))*256 + g*64 + oo;
                unsigned* dst = BgBuf + ((s+1)&1)*768;
                #pragma unroll
                for (int kq = 0; kq < 4; kq++){
                    int kp = kp2 + kq*2;
                    dst[oo*BSTR + kp] = src[(size_t)kp*256];
                }
            }
            const unsigned* Bg = BgBuf + (s&1)*768;
            int dy = s/3, dx = s - dy*3;
            const unsigned* Abase = As + ((yy+dy)*66 + dx)*ASTR + qk;
            unsigned a[2][4];
            #pragma unroll
            for (int mt = 0; mt < 2; mt++){
                const unsigned* Ap = Abase + (x0 + mt*16 + quad)*ASTR;
                a[mt][0] = Ap[0];
                a[mt][2] = Ap[4];
                a[mt][1] = Ap[8*ASTR];
                a[mt][3] = Ap[8*ASTR + 4];
            }
            #pragma unroll
            for (int nt = 0; nt < 8; nt++){
                const unsigned* Bp = Bg + (nt*8 + quad)*BSTR + qk;
                unsigned b0 = Bp[0];
                unsigned b1 = Bp[4];
                mma_bf16(acc[0][nt], a[0], b0, b1);
                mma_bf16(acc[1][nt], a[1], b0, b1);
            }
            asm volatile("bar.sync %0, 128;" :: "r"(g+1));
        }
    }
    __syncthreads();
    float* epi = (float*)smu + g*(128*17);
    int py = ytile;
    #pragma unroll
    for (int nq = 0; nq < 4; nq++){
        #pragma unroll
        for (int mt = 0; mt < 2; mt++){
            int row0 = wm*32 + mt*16 + quad;
            #pragma unroll
            for (int j = 0; j < 2; j++){
                int nt = nq*2 + j;
                int nn = j*8 + qk*2;
                epi[ row0   *17 + nn]   = acc[mt][nt][0];
                epi[ row0   *17 + nn+1] = acc[mt][nt][1];
                epi[(row0+8)*17 + nn]   = acc[mt][nt][2];
                epi[(row0+8)*17 + nn+1] = acc[mt][nt][3];
            }
        }
        asm volatile("bar.sync %0, 128;" :: "r"(g+1));
        for (int e = gtid; e < 512; e += 128){
            int px = e >> 4, oc = e & 15;
            int m0 = px*2;
            float v = fmaxf(fmaxf(epi[ m0   *17 + oc], epi[(m0+1 )*17 + oc]),
                            fmaxf(epi[(m0+64)*17 + oc], epi[(m0+65)*17 + oc]));
            int och = g*64 + nq*16 + oc;
            g_enc[((size_t)b*LPOS + py*WF + px)*CENC + och] = fmaxf(v + conv_b[och], 0.f);
        }
        asm volatile("bar.sync %0, 128;" :: "r"(g+1));
    }
    for (int e = tid; e < WF*40; e += 512){
        int px = e / 40, c40 = e % 40;
        float v = (c40 < 32) ? x_emb[px*XOH + c40] : y_emb[py*YOH + (c40-32)];
        g_enc[((size_t)b*LPOS + py*WF + px)*CENC + 256 + c40] = v;
    }
}

// ---------------- K3: giw gather GEMM ----------------
#define BM 64
#define BN 64
#define BK 16
__global__ __launch_bounds__(256) void gemm_giw(const float* __restrict__ emb,
                                                const int* __restrict__ dec_t){
    __shared__ __align__(16) float As[BK*68];
    __shared__ __align__(16) float Bs[BK*68];
    const int M = TLEN*BATCH, N = 768, K = NC;
    int m0 = blockIdx.x * BM, n0 = blockIdx.y * BN;
    int tid = threadIdx.x;
    int ty = tid >> 4, tx = tid & 15;
    float acc[4][4];
    #pragma unroll
    for (int i=0;i<4;i++){ acc[i][0]=0.f; acc[i][1]=0.f; acc[i][2]=0.f; acc[i][3]=0.f; }

    for (int k0 = 0; k0 < K; k0 += BK){
        #pragma unroll
        for (int e = tid; e < BM*BK; e += 256){
            int ml = e >> 4, kk = e & 15;
            int m = m0 + ml, k = k0 + kk;
            float v = 0.f;
            if (m < M && k < K){
                int tt = m >> 7, bb = m & 127;
                int row = (tt == 0) ? 0 : dec_t[bb*TLEN + (tt-1)];
                v = emb[(size_t)row*NC + k];
            }
            As[kk*68 + ml] = v;
        }
        #pragma unroll
        for (int e = tid; e < BN*BK; e += 256){
            int nl = e >> 4, kk = e & 15;
            int n = n0 + nl, k = k0 + kk;
            float v = 0.f;
            if (k < K) v = g_wc[(size_t)n*NC + k];
            Bs[kk*68 + nl] = v;
        }
        __syncthreads();
        #pragma unroll
        for (int kk = 0; kk < BK; kk++){
            float4 a = *(const float4*)&As[kk*68 + ty*4];
            float4 bb = *(const float4*)&Bs[kk*68 + tx*4];
            float av[4] = {a.x, a.y, a.z, a.w};
            float bv[4] = {bb.x, bb.y, bb.z, bb.w};
            #pragma unroll
            for (int i=0;i<4;i++)
                #pragma unroll
                for (int j=0;j<4;j++) acc[i][j] += av[i]*bv[j];
        }
        __syncthreads();
    }
    #pragma unroll
    for (int i=0;i<4;i++){
        int m = m0 + ty*4 + i;
        #pragma unroll
        for (int j=0;j<4;j++){
            int n = n0 + tx*4 + j;
            g_giw[((size_t)(m>>7)*N + n)*128 + (m&127)] = acc[i][j] + g_bc[n];
        }
    }
}

// ---------------- K4: tf32 MMA GEMM -> f16x2 pre ----------------
#define GM 128
#define GN 64
#define GAPAD 20
#define GBPAD 20
__global__ __launch_bounds__(256) void gemm_mma(const float* __restrict__ A, int lda,
                                                const float* __restrict__ B, int ldb,
                                                const float* __restrict__ bias, int K){
    __shared__ float As[GM*GAPAD];
    __shared__ float Bs[GN*GBPAD];
    int m0 = blockIdx.x*GM, n0 = blockIdx.y*GN;
    int tid = threadIdx.x, w = tid>>5, lane = tid&31;
    int wm = w & 3, wn = w >> 2;
    int quad = lane >> 2, qk = lane & 3;
    float acc[2][4][4];
    #pragma unroll
    for (int i=0;i<2;i++)
        #pragma unroll
        for (int j=0;j<4;j++){ acc[i][j][0]=0.f; acc[i][j][1]=0.f; acc[i][j][2]=0.f; acc[i][j][3]=0.f; }

    int nk = (K + 15)/16;
    for (int ki = 0; ki < nk; ki++){
        int k0 = ki*16;
        __syncthreads();
        #pragma unroll
        for (int j = 0; j < 2; j++){
            int idx = tid + j*256;
            int row = idx >> 2, kq = idx & 3;
            int k = k0 + kq*4;
            const float* ap = A + (size_t)(m0+row)*lda + k;
            float4 v;
            if (k + 3 < K) v = *(const float4*)ap;
            else {
                v.x = (k   < K) ? ap[0] : 0.f;
                v.y = (k+1 < K) ? ap[1] : 0.f;
                v.z = (k+2 < K) ? ap[2] : 0.f;
                v.w = (k+3 < K) ? ap[3] : 0.f;
            }
            float* d = As + row*GAPAD + kq*4;
            d[0]=tf32r(v.x); d[1]=tf32r(v.y); d[2]=tf32r(v.z); d[3]=tf32r(v.w);
        }
        {
            int row = tid >> 2, kq = tid & 3;
            int k = k0 + kq*4;
            const float* bp = B + (size_t)(n0+row)*ldb + k;
            float4 v;
            if (k + 3 < K) v = *(const float4*)bp;
            else {
                v.x = (k   < K) ? bp[0] : 0.f;
                v.y = (k+1 < K) ? bp[1] : 0.f;
                v.z = (k+2 < K) ? bp[2] : 0.f;
                v.w = (k+3 < K) ? bp[3] : 0.f;
            }
            float* d = Bs + row*GBPAD + kq*4;
            d[0]=tf32r(v.x); d[1]=tf32r(v.y); d[2]=tf32r(v.z); d[3]=tf32r(v.w);
        }
        __syncthreads();
        #pragma unroll
        for (int k8 = 0; k8 < 2; k8++){
            unsigned a[2][4];
            #pragma unroll
            for (int mf = 0; mf < 2; mf++){
                const float* Ap = As + (wm*32 + mf*16 + quad)*GAPAD + k8*8 + qk;
                a[mf][0] = __float_as_uint(Ap[0]);
                a[mf][2] = __float_as_uint(Ap[4]);
                a[mf][1] = __float_as_uint(Ap[8*GAPAD]);
                a[mf][3] = __float_as_uint(Ap[8*GAPAD+4]);
            }
            #pragma unroll
            for (int nf = 0; nf < 4; nf++){
                const float* Bp = Bs + (wn*32 + nf*8 + quad)*GBPAD + k8*8 + qk;
                unsigned b0 = __float_as_uint(Bp[0]);
                unsigned b1 = __float_as_uint(Bp[4]);
                mma_tf32(acc[0][nf], a[0], b0, b1);
                mma_tf32(acc[1][nf], a[1], b0, b1);
            }
        }
    }
    #pragma unroll
    for (int mf = 0; mf < 2; mf++){
        #pragma unroll
        for (int nf = 0; nf < 4; nf++){
            int m = m0 + wm*32 + mf*16 + quad;
            int n = n0 + wn*32 + nf*8 + qk*2;
            float bi0 = bias[n], bi1 = bias[n+1];
            g_preh[(size_t)m*128 + (n>>1)]     = pkhf(acc[mf][nf][0] + bi0, acc[mf][nf][1] + bi1);
            g_preh[(size_t)(m+8)*128 + (n>>1)] = pkhf(acc[mf][nf][2] + bi0, acc[mf][nf][3] + bi1);
        }
    }
}

// ---------------- K5: zero hidden state ----------------
__global__ void zero_h_kernel(){
    int idx = blockIdx.x*256 + threadIdx.x;
    if (idx < HID*BATCH) g_hT[idx] = 0.f;
}

// ---------------- K6: persistent decoder (512 threads) ----------------
__global__ __launch_bounds__(512) void decoder_kernel(
    const float* __restrict__ attn_v, const float* __restrict__ attn_w,
    const float* __restrict__ whh, const float* __restrict__ bhh,
    const float* __restrict__ wih, const float* __restrict__ out_w,
    const float* __restrict__ out_b, const int* __restrict__ word_t,
    float* __restrict__ out)
{
    __shared__ float s_Wb[2560];
    __shared__ float s_Ws[6*CENC];
    __shared__ float s_bias[12];
    __shared__ __align__(16) float s_vv[256];
    __shared__ __align__(16) unsigned s_hph[128];
    __shared__ __align__(16) float s_sm[6144];
    __shared__ unsigned s_ep;

    int cta = blockIdx.x, tid = threadIdx.x;
    int b127 = tid & 127;
    int kh   = tid >> 8;            // 0/1: k-half for P1
    int half = (tid >> 7) & 1;      // row parity
    int jj0 = cta*10;
    int bsel = cta;
    int hh0 = cta*2;
    int warp = tid >> 5, lane = tid & 31;

    for (int idx = tid; idx < 2560; idx += 512){
        int r = idx >> 8, k = idx & 255;
        int j = jj0 + r;
        float v = 0.f;
        if (j < 256)        v = attn_w[j*552 + k];
        else if (j < 1024)  v = whh[(j-256)*256 + k];
        else if (j < 1187)  v = out_w[(j-1024)*256 + k];
        s_Wb[r*256 + k] = v;
    }
    if (tid < 10){
        int j = jj0 + tid;
        float v = 0.f;
        if (j >= 256 && j < 1024)       v = bhh[j-256];
        else if (j >= 1024 && j < 1187) v = out_b[j-1024];
        s_bias[tid] = v;
    }
    for (int idx = tid; idx < 6*CENC; idx += 512){
        int r = idx / CENC, c = idx - r*CENC;
        int rhalf = r / 3, gate = r - rhalf*3;
        int j = gate*256 + hh0 + rhalf;
        s_Ws[idx] = wih[j*552 + 256 + c];
    }
    if (tid < 256) s_vv[tid] = attn_v[tid];
    if (tid == 0) s_ep = ld_acq(&g_bar_epoch);
    __syncthreads();
    unsigned bt = s_ep;

    for (int it = 0; it <= TLEN; it++){
        // ---- P1: rows jj0..jj0+9, k-split across kh ----
        {
            float a0=0.f, a1=0.f, a2=0.f, a3=0.f, a4=0.f;
            const float* hcol = g_hT + b127;
            int kbase = kh*128;
            #pragma unroll 2
            for (int k = 0; k < 128; k += 4){
                int kk = kbase + k;
                float hv0 = hcol[(kk+0)*128];
                float hv1 = hcol[(kk+1)*128];
                float hv2 = hcol[(kk+2)*128];
                float hv3 = hcol[(kk+3)*128];
                float4 w0 = *(const float4*)&s_Wb[(half+0)*256 + kk];
                float4 w1 = *(const float4*)&s_Wb[(half+2)*256 + kk];
                float4 w2 = *(const float4*)&s_Wb[(half+4)*256 + kk];
                float4 w3 = *(const float4*)&s_Wb[(half+6)*256 + kk];
                float4 w4 = *(const float4*)&s_Wb[(half+8)*256 + kk];
                a0 += w0.x*hv0 + w0.y*hv1 + w0.z*hv2 + w0.w*hv3;
                a1 += w1.x*hv0 + w1.y*hv1 + w1.z*hv2 + w1.w*hv3;
                a2 += w2.x*hv0 + w2.y*hv1 + w2.z*hv2 + w2.w*hv3;
                a3 += w3.x*hv0 + w3.y*hv1 + w3.z*hv2 + w3.w*hv3;
                a4 += w4.x*hv0 + w4.y*hv1 + w4.z*hv2 + w4.w*hv3;
            }
            if (kh == 1){
                s_sm[(half+0)*128 + b127] = a0;
                s_sm[(half+2)*128 + b127] = a1;
                s_sm[(half+4)*128 + b127] = a2;
                s_sm[(half+6)*128 + b127] = a3;
                s_sm[(half+8)*128 + b127] = a4;
            }
            __syncthreads();
            if (kh == 0){
                g_hcatT[(size_t)(jj0+half+0)*128 + b127] = a0 + s_sm[(half+0)*128 + b127] + s_bias[half+0];
                g_hcatT[(size_t)(jj0+half+2)*128 + b127] = a1 + s_sm[(half+2)*128 + b127] + s_bias[half+2];
                g_hcatT[(size_t)(jj0+half+4)*128 + b127] = a2 + s_sm[(half+4)*128 + b127] + s_bias[half+4];
                g_hcatT[(size_t)(jj0+half+6)*128 + b127] = a3 + s_sm[(half+6)*128 + b127] + s_bias[half+6];
                g_hcatT[(size_t)(jj0+half+8)*128 + b127] = a4 + s_sm[(half+8)*128 + b127] + s_bias[half+8];
            }
        }
        grid_barrier(++bt);
        // ---- nll for t = it-1 ----
        if (it >= 1){
            float* lg  = s_sm;
            float* red = s_sm + 192;
            float lv = -1e30f;
            if (tid < NC){ lv = g_hcatT[(size_t)(1024+tid)*128 + bsel]; lg[tid] = lv; }
            if (tid < 256) red[tid] = lv;
            __syncthreads();
            for (int s = 128; s; s >>= 1){ if (tid < s) red[tid] = fmaxf(red[tid], red[tid+s]); __syncthreads(); }
            float mx = red[0]; __syncthreads();
            if (tid < 256) red[tid] = (tid < NC) ? __expf(lg[tid] - mx) : 0.f;
            __syncthreads();
            for (int s = 128; s; s >>= 1){ if (tid < s) red[tid] += red[tid+s]; __syncthreads(); }
            if (tid == 0){
                float lse = mx + logf(red[0]);
                int tgt = word_t[bsel*TLEN + (it-1)];
                float v = 0.f;
                if (tgt >= 0){
                    int tc = tgt > (NC-1) ? (NC-1) : tgt;
                    v = lse - lg[tc];
                }
                g_nll[(it-1)*BATCH + bsel] = v;
            }
            __syncthreads();
        }
        if (it == TLEN) break;
        // ---- P2: attention ----
        {
            float* hp  = s_sm + 448;
            float* sc  = s_sm + 704;
            float* red = s_sm + 960;
            if (tid < 256) hp[tid] = g_hcatT[(size_t)tid*128 + bsel];
            __syncthreads();
            if (tid < 128) s_hph[tid] = pkhf(hp[2*tid], hp[2*tid+1]);
            __syncthreads();
            const unsigned* pb = g_preh + (size_t)bsel*LPOS*128;
            for (int l = warp; l < LPOS; l += 32){
                const unsigned* p1 = pb + (size_t)l*128;
                const unsigned* p2 = p1 + 16*128;
                float s1 = 0.f, s2 = 0.f;
                #pragma unroll
                for (int i = 0; i < 4; i++){
                    int p = lane + 32*i;
                    unsigned hv = s_hph[p];
                    unsigned t1 = tanh2u(hadd2u(p1[p], hv));
                    unsigned t2 = tanh2u(hadd2u(p2[p], hv));
                    float2 f1 = uph(t1);
                    float2 f2 = uph(t2);
                    float2 vp = *(const float2*)&s_vv[2*p];
                    s1 += vp.x*f1.x + vp.y*f1.y;
                    s2 += vp.x*f2.x + vp.y*f2.y;
                }
                s1 = warp_sum(s1);
                s2 = warp_sum(s2);
                if (lane == 0){ sc[l] = s1; sc[l+16] = s2; }
            }
            __syncthreads();
            if (tid < 256) red[tid] = sc[tid];
            __syncthreads();
            for (int s = 128; s; s >>= 1){ if (tid < s) red[tid] = fmaxf(red[tid], red[tid+s]); __syncthreads(); }
            float mx = red[0]; __syncthreads();
            float e = 0.f;
            if (tid < 256){ e = __expf(sc[tid] - mx); red[tid] = e; }
            __syncthreads();
            for (int s = 128; s; s >>= 1){ if (tid < s) red[tid] += red[tid+s]; __syncthreads(); }
            float inv = 1.f / red[0]; __syncthreads();
            if (tid < 256) sc[tid] = e * inv;
            __syncthreads();
            // ctx: 16-way warp split over l
            {
                float part[10];
                #pragma unroll
                for (int i = 0; i < 10; i++) part[i] = 0.f;
                const float* eb = g_enc + (size_t)bsel*LPOS*CENC;
                int lbase = warp*16;
                for (int ll = 0; ll < 16; ll++){
                    int l = lbase + ll;
                    float wl = sc[l];
                    const float* er = eb + (size_t)l*CENC;
                    #pragma unroll
                    for (int i = 0; i < 9; i++)
                        part[i] += wl * er[lane + 32*i];
                    if (lane < 8) part[9] += wl * er[288 + lane];
                }
                float* pp = s_sm + 1216;   // 16 x 296 = 4736
                #pragma unroll
                for (int i = 0; i < 9; i++) pp[warp*CENC + lane + 32*i] = part[i];
                if (lane < 8) pp[warp*CENC + 288 + lane] = part[9];
                __syncthreads();
                for (int c = tid; c < CENC; c += 512){
                    float a = 0.f;
                    #pragma unroll
                    for (int wq = 0; wq < 16; wq++) a += pp[wq*CENC + c];
                    g_ctxT[(size_t)c*128 + bsel] = a;
                }
            }
        }
        grid_barrier(++bt);
        // ---- P3: gi + gates -> h ----
        {
            float* cs = s_sm;
            float ar = 0.f, az = 0.f, an = 0.f;
            int hh = hh0 + half;
            for (int c0 = 0; c0 < CENC; c0 += 48){
                int len = (CENC - c0) < 48 ? (CENC - c0) : 48;
                __syncthreads();
                for (int idx = tid; idx < len*128; idx += 512)
                    cs[idx] = g_ctxT[(size_t)c0*128 + idx];
                __syncthreads();
                if (tid < 256){
                    for (int cc = 0; cc < len; cc++){
                        float cv = cs[cc*128 + b127];
                        int c = c0 + cc;
                        ar += s_Ws[(half*3+0)*CENC + c]*cv;
                        az += s_Ws[(half*3+1)*CENC + c]*cv;
                        an += s_Ws[(half*3+2)*CENC + c]*cv;
                    }
                }
            }
            if (tid < 256){
                const float* giw = g_giw + (size_t)it*768*128;
                int hh2 = hh;
                float gir = giw[(size_t)(      hh2)*128 + b127] + ar;
                float giz = giw[(size_t)(256 + hh2)*128 + b127] + az;
                float gin = giw[(size_t)(512 + hh2)*128 + b127] + an;
                float ghr = g_hcatT[(size_t)(256 +       hh2)*128 + b127];
                float ghz = g_hcatT[(size_t)(256 + 256 + hh2)*128 + b127];
                float ghn = g_hcatT[(size_t)(256 + 512 + hh2)*128 + b127];
                float r = 1.f/(1.f + __expf(-(gir + ghr)));
                float z = 1.f/(1.f + __expf(-(giz + ghz)));
                float n = tanhf(gin + r*ghn);
                float ho = g_hT[hh2*128 + b127];
                g_hT[hh2*128 + b127] = (1.f - z)*n + z*ho;
            }
        }
        grid_barrier(++bt);
    }
    grid_barrier(++bt);
    if (cta == 0){
        float* red = s_sm;
        float s = 0.f;
        for (int i = tid; i < TLEN*BATCH; i += 512) s += g_nll[i];
        red[tid] = s; __syncthreads();
        for (int k = 256; k; k >>= 1){ if (tid < k) red[tid] += red[tid+k]; __syncthreads(); }
        if (tid == 0) out[0] = 0.2f * red[0] / (float)BATCH;
    }
}

// ---------------- host ----------------
extern "C" void kernel_launch(void* const* d_in, const int* in_sizes, int n_in,
                              void* d_out, int out_size){
    const float* x        = (const float*)d_in[0];
    const int*   dec_t    = (const int*)  d_in[1];
    const int*   word_t   = (const int*)  d_in[2];
    const float* conv_w   = (const float*)d_in[3];
    const float* conv_b   = (const float*)d_in[4];
    const float* emb_dec  = (const float*)d_in[5];
    const float* word_w   = (const float*)d_in[6];
    const float* word_b   = (const float*)d_in[7];
    const float* attn_w   = (const float*)d_in[8];
    const float* attn_b   = (const float*)d_in[9];
    const float* attn_v   = (const float*)d_in[10];
    const float* gru_wih  = (const float*)d_in[11];
    const float* gru_bih  = (const float*)d_in[12];
    const float* gru_whh  = (const float*)d_in[13];
    const float* gru_bhh  = (const float*)d_in[14];
    const float* out_w    = (const float*)d_in[15];
    const float* out_b    = (const float*)d_in[16];
    const float* x_emb    = (const float*)d_in[17];
    const float* y_emb    = (const float*)d_in[18];
    float* out = (float*)d_out;

    float *p_enc = nullptr;
    cudaGetSymbolAddress((void**)&p_enc, g_enc);

    prep_kernel<<<RES_BLKS + WRB_BLKS + WC_BLKS, 256>>>(x, conv_w, gru_wih, gru_bih,
                                                        word_w, word_b);
    conv_mma_kernel<<<dim3(BATCH, 8), 512>>>(conv_b, x_emb, y_emb);
    gemm_giw<<<dim3((TLEN*BATCH)/BM, 768/BN), 256>>>(emb_dec, dec_t);
    gemm_mma<<<dim3((BATCH*LPOS)/GM, HID/GN), 256>>>(
        p_enc, CENC, attn_w + 256, 552, attn_b, CENC);
    zero_h_kernel<<<(HID*BATCH + 255)/256, 256>>>();
    decoder_kernel<<<BATCH, 512>>>(attn_v, attn_w, gru_whh, gru_bhh, gru_wih,
                                   out_w, out_b, word_t, out);
    (void)in_sizes; (void)n_in; (void)out_size;
}

// round 14
// speedup vs baseline: 1.0437x; 1.0437x over previous
#include <cuda_runtime.h>
#include <cuda_bf16.h>
#include <cuda_fp16.h>
#include <math.h>

// ---------------- Problem constants ----------------
#define BATCH   128
#define CIN     256
#define HIN     8
#define WIN     32
#define RH      16
#define RW      64
#define HF      8
#define WF      32
#define LPOS    256
#define XOH     32
#define YOH     8
#define CENC    296
#define HID     256
#define NC      163
#define TLEN    32

#define PADH    18
#define PADW    66
#define CPAIR   148     // CENC/2

// ---------------- Scratch ----------------
__device__ float    g_resT[BATCH*PADH*PADW*CIN];
__device__ unsigned g_wrb [9*128*256];
__device__ float    g_wc  [768*NC];
__device__ float    g_bc  [768];
__device__ float    g_enc [BATCH*LPOS*CENC];      // fp32 (pre-GEMM input)
__device__ unsigned g_ench[BATCH*LPOS*CPAIR];     // f16x2 (ctx input)
__device__ unsigned g_preh[BATCH*LPOS*128];
__device__ float    g_giw[TLEN*768*BATCH];
__device__ float    g_hT   [HID*BATCH];
__device__ float    g_hcatT[1280*BATCH];
__device__ float    g_ctxT [CENC*BATCH];
__device__ float    g_nll  [TLEN*BATCH];
__device__ unsigned g_bar_arrive;
__device__ unsigned g_bar_epoch;

// ---------------- helpers ----------------
__device__ __forceinline__ float warp_sum(float v){
    #pragma unroll
    for (int o = 16; o; o >>= 1) v += __shfl_down_sync(0xffffffffu, v, o);
    return v;
}
__device__ __forceinline__ float tf32r(float f){
    unsigned u; asm("cvt.rna.tf32.f32 %0, %1;" : "=r"(u) : "f"(f));
    return __uint_as_float(u);
}
__device__ __forceinline__ unsigned pkbf(float a, float b){
    __nv_bfloat162 h = __floats2bfloat162_rn(a, b);
    return *(unsigned*)&h;
}
__device__ __forceinline__ unsigned pkhf(float a, float b){
    __half2 h = __floats2half2_rn(a, b);
    return *(unsigned*)&h;
}
__device__ __forceinline__ unsigned hadd2u(unsigned a, unsigned b){
    unsigned r; asm("add.f16x2 %0, %1, %2;" : "=r"(r) : "r"(a), "r"(b)); return r;
}
__device__ __forceinline__ unsigned tanh2u(unsigned a){
    unsigned r; asm("tanh.approx.f16x2 %0, %1;" : "=r"(r) : "r"(a)); return r;
}
__device__ __forceinline__ float2 uph(unsigned u){
    return __half22float2(*(__half2*)&u);
}
__device__ __forceinline__ void mma_tf32(float* c, const unsigned* a, unsigned b0, unsigned b1){
    asm volatile("mma.sync.aligned.m16n8k8.row.col.f32.tf32.tf32.f32 "
        "{%0,%1,%2,%3}, {%4,%5,%6,%7}, {%8,%9}, {%0,%1,%2,%3};"
        : "+f"(c[0]), "+f"(c[1]), "+f"(c[2]), "+f"(c[3])
        : "r"(a[0]), "r"(a[1]), "r"(a[2]), "r"(a[3]), "r"(b0), "r"(b1));
}
__device__ __forceinline__ void mma_bf16(float* c, const unsigned* a, unsigned b0, unsigned b1){
    asm volatile("mma.sync.aligned.m16n8k16.row.col.f32.bf16.bf16.f32 "
        "{%0,%1,%2,%3}, {%4,%5,%6,%7}, {%8,%9}, {%0,%1,%2,%3};"
        : "+f"(c[0]), "+f"(c[1]), "+f"(c[2]), "+f"(c[3])
        : "r"(a[0]), "r"(a[1]), "r"(a[2]), "r"(a[3]), "r"(b0), "r"(b1));
}
__device__ __forceinline__ unsigned ld_acq(unsigned* p){
    unsigned v; asm volatile("ld.acquire.gpu.u32 %0, [%1];" : "=r"(v) : "l"(p)); return v;
}
__device__ __forceinline__ void grid_barrier(unsigned target){
    __syncthreads();
    if (threadIdx.x == 0){
        unsigned t;
        asm volatile("atom.acq_rel.gpu.global.add.u32 %0, [%1], 1;"
                     : "=r"(t) : "l"(&g_bar_arrive) : "memory");
        if (t == gridDim.x - 1){
            g_bar_arrive = 0u;
            asm volatile("red.release.gpu.global.add.u32 [%0], 1;" :: "l"(&g_bar_epoch) : "memory");
        } else {
            while ((int)(ld_acq(&g_bar_epoch) - target) < 0) __nanosleep(64);
        }
    }
    __syncthreads();
}

// ---------------- K1: fused prep (resize + conv-w pack + Wc fold + zero h) ----------------
#define RES_BLKS  (8*PADH*BATCH)
#define WRB_BLKS  ((9*128*256)/256)
#define WC_BLKS   (768/4)
#define ZH_BLKS   ((HID*BATCH)/256)
__global__ __launch_bounds__(256) void prep_kernel(
    const float* __restrict__ x, const float* __restrict__ conv_w,
    const float* __restrict__ wih, const float* __restrict__ bih,
    const float* __restrict__ word_w, const float* __restrict__ word_b)
{
    __shared__ float smem_u[32*67];
    int bid = blockIdx.x;
    int t = threadIdx.x;
    if (bid < RES_BLKS){
        float (*tile)[67] = (float(*)[67])smem_u;
        int cg = bid % 8;
        int yp = (bid / 8) % PADH;
        int b  = bid / (8*PADH);
        int xo  = t & 63;
        int cl0 = (t >> 6)*8;
        bool interior = (yp >= 1 && yp <= 16);
        int y0c = 0, y1c = 0; float fy = 0.f;
        if (interior){
            float sy = 0.5f*(yp-1) - 0.25f;
            int y0 = (int)floorf(sy); fy = sy - (float)y0;
            y0c = y0 < 0 ? 0 : y0;
            y1c = (y0+1) > (HIN-1) ? (HIN-1) : (y0+1);
        }
        float sx = 0.5f*xo - 0.25f;
        int x0 = (int)floorf(sx); float fx = sx - (float)x0;
        int x0c = x0 < 0 ? 0 : x0;
        int x1c = (x0+1) > (WIN-1) ? (WIN-1) : (x0+1);
        #pragma unroll
        for (int i = 0; i < 8; i++){
            int cl = cl0 + i;
            float v = 0.f;
            if (interior){
                const float* base = x + (size_t)(b*CIN + cg*32 + cl)*(HIN*WIN);
                float v00 = base[y0c*WIN + x0c], v01 = base[y0c*WIN + x1c];
                float v10 = base[y1c*WIN + x0c], v11 = base[y1c*WIN + x1c];
                v = (1.f-fy)*((1.f-fx)*v00 + fx*v01) + fy*((1.f-fx)*v10 + fx*v11);
            }
            tile[cl][xo+1] = v;
        }
        if (t < 32){ tile[t][0] = 0.f; tile[t][65] = 0.f; }
        __syncthreads();
        int warp = t >> 5, lane = t & 31;
        for (int xp = warp; xp < PADW; xp += 8){
            g_resT[(((size_t)b*PADH + yp)*PADW + xp)*CIN + cg*32 + lane] = tile[lane][xp];
        }
    } else if (bid < RES_BLKS + WRB_BLKS){
        int idx = (bid - RES_BLKS)*256 + t;
        int o  = idx & 255;
        int kp = (idx >> 8) & 127;
        int s  = idx >> 15;
        float f0 = conv_w[((size_t)o*CIN + 2*kp  )*9 + s];
        float f1 = conv_w[((size_t)o*CIN + 2*kp+1)*9 + s];
        g_wrb[idx] = pkbf(f0, f1);
    } else if (bid < RES_BLKS + WRB_BLKS + WC_BLKS){
        int j0 = (bid - RES_BLKS - WRB_BLKS)*4;
        float* s_wih = smem_u;
        for (int idx = t; idx < 1024; idx += 256){
            int r = idx >> 8, k = idx & 255;
            s_wih[idx] = wih[(size_t)(j0+r)*552 + k];
        }
        __syncthreads();
        if (t < NC){
            float a0=0.f, a1=0.f, a2=0.f, a3=0.f;
            for (int k = 0; k < 256; k++){
                float wv = word_w[k*NC + t];
                a0 += s_wih[      k]*wv;
                a1 += s_wih[256 + k]*wv;
                a2 += s_wih[512 + k]*wv;
                a3 += s_wih[768 + k]*wv;
            }
            g_wc[(size_t)(j0+0)*NC + t] = a0;
            g_wc[(size_t)(j0+1)*NC + t] = a1;
            g_wc[(size_t)(j0+2)*NC + t] = a2;
            g_wc[(size_t)(j0+3)*NC + t] = a3;
        }
        if (t < 4){
            float s = bih[j0 + t];
            for (int k = 0; k < 256; k++) s += s_wih[t*256 + k]*word_b[k];
            g_bc[j0 + t] = s;
        }
    } else {
        int idx = (bid - RES_BLKS - WRB_BLKS - WC_BLKS)*256 + t;
        g_hT[idx] = 0.f;
    }
}

// ---------------- K2: conv3x3 bf16 MMA, double-buffered B, f16x2 enc epilogue ----------------
#define ASTR 12
#define BSTR 12
#define AS_U (4*66*ASTR)
#define BS2_U (2*64*BSTR)
#define SMU_SZ (AS_U + 4*BS2_U)
__global__ __launch_bounds__(512, 1) void conv_mma_kernel(const float* __restrict__ conv_b,
                                                          const float* __restrict__ x_emb,
                                                          const float* __restrict__ y_emb){
    __shared__ __align__(16) unsigned smu[SMU_SZ];
    unsigned* As = smu;
    unsigned* Bs = smu + AS_U;
    int b = blockIdx.x, ytile = blockIdx.y;
    int y0 = ytile*2;
    int tid = threadIdx.x;
    int w = tid >> 5, lane = tid & 31;
    int wm = w & 3, g = w >> 2;
    int quad = lane >> 2, qk = lane & 3;
    int gtid = tid & 127;
    unsigned* BgBuf = Bs + g*BS2_U;
    int yy = wm >> 1;
    int x0 = (wm & 1) << 5;
    int kp2 = gtid >> 6, oo = gtid & 63;

    float acc[2][8][4];
    #pragma unroll
    for (int i=0;i<2;i++)
        #pragma unroll
        for (int j=0;j<8;j++){ acc[i][j][0]=0.f; acc[i][j][1]=0.f; acc[i][j][2]=0.f; acc[i][j][3]=0.f; }

    const float* srcA = g_resT + (size_t)(b*PADH + y0) * (PADW*CIN);
    for (int chunk = 0; chunk < 16; chunk++){
        int c0 = chunk*16;
        __syncthreads();
        for (int e4 = tid; e4 < 4*66*4; e4 += 512){
            int c4 = e4 & 3;
            int xr = (e4 >> 2) % 66;
            int r  = e4 / 264;
            float4 v = *(const float4*)(srcA + ((size_t)r*PADW + xr)*CIN + c0 + c4*4);
            unsigned* d = As + (r*66 + xr)*ASTR + c4*2;
            d[0] = pkbf(v.x, v.y);
            d[1] = pkbf(v.z, v.w);
        }
        __syncthreads();
        {
            const unsigned* src = g_wrb + ((size_t)(chunk*8))*256 + g*64 + oo;
            unsigned* dst = BgBuf;
            #pragma unroll
            for (int kq = 0; kq < 4; kq++){
                int kp = kp2 + kq*2;
                dst[oo*BSTR + kp] = src[(size_t)kp*256];
            }
        }
        asm volatile("bar.sync %0, 128;" :: "r"(g+1));
        for (int s = 0; s < 9; s++){
            if (s < 8){
                const unsigned* src = g_wrb + ((size_t)((s+1)*128 + chunk*8))*256 + g*64 + oo;
                unsigned* dst = BgBuf + ((s+1)&1)*768;
                #pragma unroll
                for (int kq = 0; kq < 4; kq++){
                    int kp = kp2 + kq*2;
                    dst[oo*BSTR + kp] = src[(size_t)kp*256];
                }
            }
            const unsigned* Bg = BgBuf + (s&1)*768;
            int dy = s/3, dx = s - dy*3;
            const unsigned* Abase = As + ((yy+dy)*66 + dx)*ASTR + qk;
            unsigned a[2][4];
            #pragma unroll
            for (int mt = 0; mt < 2; mt++){
                const unsigned* Ap = Abase + (x0 + mt*16 + quad)*ASTR;
                a[mt][0] = Ap[0];
                a[mt][2] = Ap[4];
                a[mt][1] = Ap[8*ASTR];
                a[mt][3] = Ap[8*ASTR + 4];
            }
            #pragma unroll
            for (int nt = 0; nt < 8; nt++){
                const unsigned* Bp = Bg + (nt*8 + quad)*BSTR + qk;
                unsigned b0 = Bp[0];
                unsigned b1 = Bp[4];
                mma_bf16(acc[0][nt], a[0], b0, b1);
                mma_bf16(acc[1][nt], a[1], b0, b1);
            }
            asm volatile("bar.sync %0, 128;" :: "r"(g+1));
        }
    }
    __syncthreads();
    float* epi = (float*)smu + g*(128*17);
    int py = ytile;
    #pragma unroll
    for (int nq = 0; nq < 4; nq++){
        #pragma unroll
        for (int mt = 0; mt < 2; mt++){
            int row0 = wm*32 + mt*16 + quad;
            #pragma unroll
            for (int j = 0; j < 2; j++){
                int nt = nq*2 + j;
                int nn = j*8 + qk*2;
                epi[ row0   *17 + nn]   = acc[mt][nt][0];
                epi[ row0   *17 + nn+1] = acc[mt][nt][1];
                epi[(row0+8)*17 + nn]   = acc[mt][nt][2];
                epi[(row0+8)*17 + nn+1] = acc[mt][nt][3];
            }
        }
        asm volatile("bar.sync %0, 128;" :: "r"(g+1));
        for (int e = gtid; e < 256; e += 128){
            int px = e >> 3, pc = e & 7;
            int m0 = px*2;
            int oc0 = 2*pc;
            float v0 = fmaxf(fmaxf(epi[ m0   *17 + oc0], epi[(m0+1 )*17 + oc0]),
                             fmaxf(epi[(m0+64)*17 + oc0], epi[(m0+65)*17 + oc0]));
            float v1 = fmaxf(fmaxf(epi[ m0   *17 + oc0+1], epi[(m0+1 )*17 + oc0+1]),
                             fmaxf(epi[(m0+64)*17 + oc0+1], epi[(m0+65)*17 + oc0+1]));
            int och0 = g*64 + nq*16 + oc0;
            float r0 = fmaxf(v0 + conv_b[och0],   0.f);
            float r1 = fmaxf(v1 + conv_b[och0+1], 0.f);
            size_t lidx = (size_t)b*LPOS + py*WF + px;
            *(float2*)&g_enc[lidx*CENC + och0] = make_float2(r0, r1);
            g_ench[lidx*CPAIR + (och0 >> 1)] = pkhf(r0, r1);
        }
        asm volatile("bar.sync %0, 128;" :: "r"(g+1));
    }
    // positional channels (pairs)
    for (int e = tid; e < WF*20; e += 512){
        int px = e / 20, pq = e % 20;
        int c0 = 2*pq;
        float v0, v1;
        if (c0 < 32){ v0 = x_emb[px*XOH + c0]; v1 = x_emb[px*XOH + c0+1]; }
        else        { v0 = y_emb[py*YOH + (c0-32)]; v1 = y_emb[py*YOH + (c0-31)]; }
        size_t lidx = (size_t)b*LPOS + py*WF + px;
        *(float2*)&g_enc[lidx*CENC + 256 + c0] = make_float2(v0, v1);
        g_ench[lidx*CPAIR + 128 + pq] = pkhf(v0, v1);
    }
}

// ---------------- K3: mid kernel = giw gather GEMM + pre tf32 GEMM ----------------
#define BM 64
#define BN 64
#define BK 16
#define GM 128
#define GN 64
#define GAPAD 20
#define GBPAD 20
#define GIW_BLKS 768    // 64 m x 12 n
#define PRE_BLKS 1024   // 256 m x 4 n
__global__ __launch_bounds__(256) void mid_kernel(
    const float* __restrict__ emb, const int* __restrict__ dec_t,
    const float* __restrict__ attn_w, const float* __restrict__ attn_b)
{
    __shared__ __align__(16) float smid[3840];
    int bid = blockIdx.x;
    int tid = threadIdx.x;
    if (bid < GIW_BLKS){
        float* As = smid;          // 16*68 = 1088
        float* Bs = smid + 1088;
        const int M = TLEN*BATCH, K = NC;
        int m0 = (bid & 63) * BM, n0 = (bid >> 6) * BN;
        int ty = tid >> 4, tx = tid & 15;
        float acc[4][4];
        #pragma unroll
        for (int i=0;i<4;i++){ acc[i][0]=0.f; acc[i][1]=0.f; acc[i][2]=0.f; acc[i][3]=0.f; }
        for (int k0 = 0; k0 < K; k0 += BK){
            #pragma unroll
            for (int e = tid; e < BM*BK; e += 256){
                int ml = e >> 4, kk = e & 15;
                int m = m0 + ml, k = k0 + kk;
                float v = 0.f;
                if (m < M && k < K){
                    int tt = m >> 7, bb = m & 127;
                    int row = (tt == 0) ? 0 : dec_t[bb*TLEN + (tt-1)];
                    v = emb[(size_t)row*NC + k];
                }
                As[kk*68 + ml] = v;
            }
            #pragma unroll
            for (int e = tid; e < BN*BK; e += 256){
                int nl = e >> 4, kk = e & 15;
                int n = n0 + nl, k = k0 + kk;
                float v = 0.f;
                if (k < K) v = g_wc[(size_t)n*NC + k];
                Bs[kk*68 + nl] = v;
            }
            __syncthreads();
            #pragma unroll
            for (int kk = 0; kk < BK; kk++){
                float4 a = *(const float4*)&As[kk*68 + ty*4];
                float4 bb = *(const float4*)&Bs[kk*68 + tx*4];
                float av[4] = {a.x, a.y, a.z, a.w};
                float bv[4] = {bb.x, bb.y, bb.z, bb.w};
                #pragma unroll
                for (int i=0;i<4;i++)
                    #pragma unroll
                    for (int j=0;j<4;j++) acc[i][j] += av[i]*bv[j];
            }
            __syncthreads();
        }
        #pragma unroll
        for (int i=0;i<4;i++){
            int m = m0 + ty*4 + i;
            #pragma unroll
            for (int j=0;j<4;j++){
                int n = n0 + tx*4 + j;
                g_giw[((size_t)(m>>7)*768 + n)*128 + (m&127)] = acc[i][j] + g_bc[n];
            }
        }
    } else {
        // pre = enc @ We^T + attn_b -> f16x2
        float* As = smid;            // 128*20 = 2560
        float* Bs = smid + 2560;     // 64*20 = 1280
        int idx = bid - GIW_BLKS;
        int m0 = (idx & 255) * GM, n0 = (idx >> 8) * GN;
        const float* A = g_enc;
        const float* B = attn_w + 256;
        const int lda = CENC, ldb = 552, K = CENC;
        int w = tid>>5, lane = tid&31;
        int wm = w & 3, wn = w >> 2;
        int quad = lane >> 2, qk = lane & 3;
        float acc[2][4][4];
        #pragma unroll
        for (int i=0;i<2;i++)
            #pragma unroll
            for (int j=0;j<4;j++){ acc[i][j][0]=0.f; acc[i][j][1]=0.f; acc[i][j][2]=0.f; acc[i][j][3]=0.f; }
        int nk = (K + 15)/16;
        for (int ki = 0; ki < nk; ki++){
            int k0 = ki*16;
            __syncthreads();
            #pragma unroll
            for (int j = 0; j < 2; j++){
                int i2 = tid + j*256;
                int row = i2 >> 2, kq = i2 & 3;
                int k = k0 + kq*4;
                const float* ap = A + (size_t)(m0+row)*lda + k;
                float4 v;
                if (k + 3 < K) v = *(const float4*)ap;
                else {
                    v.x = (k   < K) ? ap[0] : 0.f;
                    v.y = (k+1 < K) ? ap[1] : 0.f;
                    v.z = (k+2 < K) ? ap[2] : 0.f;
                    v.w = (k+3 < K) ? ap[3] : 0.f;
                }
                float* d = As + row*GAPAD + kq*4;
                d[0]=tf32r(v.x); d[1]=tf32r(v.y); d[2]=tf32r(v.z); d[3]=tf32r(v.w);
            }
            {
                int row = tid >> 2, kq = tid & 3;
                int k = k0 + kq*4;
                const float* bp = B + (size_t)(n0+row)*ldb + k;
                float4 v;
                if (k + 3 < K) v = *(const float4*)bp;
                else {
                    v.x = (k   < K) ? bp[0] : 0.f;
                    v.y = (k+1 < K) ? bp[1] : 0.f;
                    v.z = (k+2 < K) ? bp[2] : 0.f;
                    v.w = (k+3 < K) ? bp[3] : 0.f;
                }
                float* d = Bs + row*GBPAD + kq*4;
                d[0]=tf32r(v.x); d[1]=tf32r(v.y); d[2]=tf32r(v.z); d[3]=tf32r(v.w);
            }
            __syncthreads();
            #pragma unroll
            for (int k8 = 0; k8 < 2; k8++){
                unsigned a[2][4];
                #pragma unroll
                for (int mf = 0; mf < 2; mf++){
                    const float* Ap = As + (wm*32 + mf*16 + quad)*GAPAD + k8*8 + qk;
                    a[mf][0] = __float_as_uint(Ap[0]);
                    a[mf][2] = __float_as_uint(Ap[4]);
                    a[mf][1] = __float_as_uint(Ap[8*GAPAD]);
                    a[mf][3] = __float_as_uint(Ap[8*GAPAD+4]);
                }
                #pragma unroll
                for (int nf = 0; nf < 4; nf++){
                    const float* Bp = Bs + (wn*32 + nf*8 + quad)*GBPAD + k8*8 + qk;
                    unsigned b0 = __float_as_uint(Bp[0]);
                    unsigned b1 = __float_as_uint(Bp[4]);
                    mma_tf32(acc[0][nf], a[0], b0, b1);
                    mma_tf32(acc[1][nf], a[1], b0, b1);
                }
            }
        }
        #pragma unroll
        for (int mf = 0; mf < 2; mf++){
            #pragma unroll
            for (int nf = 0; nf < 4; nf++){
                int m = m0 + wm*32 + mf*16 + quad;
                int n = n0 + wn*32 + nf*8 + qk*2;
                float bi0 = attn_b[n], bi1 = attn_b[n+1];
                g_preh[(size_t)m*128 + (n>>1)]     = pkhf(acc[mf][nf][0] + bi0, acc[mf][nf][1] + bi1);
                g_preh[(size_t)(m+8)*128 + (n>>1)] = pkhf(acc[mf][nf][2] + bi0, acc[mf][nf][3] + bi1);
            }
        }
    }
}

// ---------------- K4: persistent decoder (512 threads) ----------------
__global__ __launch_bounds__(512) void decoder_kernel(
    const float* __restrict__ attn_v, const float* __restrict__ attn_w,
    const float* __restrict__ whh, const float* __restrict__ bhh,
    const float* __restrict__ wih, const float* __restrict__ out_w,
    const float* __restrict__ out_b, const int* __restrict__ word_t,
    float* __restrict__ out)
{
    __shared__ float s_Wb[2560];
    __shared__ float s_Ws[6*CENC];
    __shared__ float s_bias[12];
    __shared__ __align__(16) float s_vv[256];
    __shared__ __align__(16) unsigned s_hph[128];
    __shared__ __align__(16) float s_sm[6144];
    __shared__ unsigned s_ep;

    int cta = blockIdx.x, tid = threadIdx.x;
    int b127 = tid & 127;
    int kh   = tid >> 8;
    int half = (tid >> 7) & 1;
    int jj0 = cta*10;
    int bsel = cta;
    int hh0 = cta*2;
    int warp = tid >> 5, lane = tid & 31;

    for (int idx = tid; idx < 2560; idx += 512){
        int r = idx >> 8, k = idx & 255;
        int j = jj0 + r;
        float v = 0.f;
        if (j < 256)        v = attn_w[j*552 + k];
        else if (j < 1024)  v = whh[(j-256)*256 + k];
        else if (j < 1187)  v = out_w[(j-1024)*256 + k];
        s_Wb[r*256 + k] = v;
    }
    if (tid < 10){
        int j = jj0 + tid;
        float v = 0.f;
        if (j >= 256 && j < 1024)       v = bhh[j-256];
        else if (j >= 1024 && j < 1187) v = out_b[j-1024];
        s_bias[tid] = v;
    }
    for (int idx = tid; idx < 6*CENC; idx += 512){
        int r = idx / CENC, c = idx - r*CENC;
        int rhalf = r / 3, gate = r - rhalf*3;
        int j = gate*256 + hh0 + rhalf;
        s_Ws[idx] = wih[j*552 + 256 + c];
    }
    if (tid < 256) s_vv[tid] = attn_v[tid];
    if (tid == 0) s_ep = ld_acq(&g_bar_epoch);
    __syncthreads();
    unsigned bt = s_ep;

    for (int it = 0; it <= TLEN; it++){
        // ---- P1: rows jj0..jj0+9, k-split across kh ----
        {
            float a0=0.f, a1=0.f, a2=0.f, a3=0.f, a4=0.f;
            const float* hcol = g_hT + b127;
            int kbase = kh*128;
            #pragma unroll 2
            for (int k = 0; k < 128; k += 4){
                int kk = kbase + k;
                float hv0 = hcol[(kk+0)*128];
                float hv1 = hcol[(kk+1)*128];
                float hv2 = hcol[(kk+2)*128];
                float hv3 = hcol[(kk+3)*128];
                float4 w0 = *(const float4*)&s_Wb[(half+0)*256 + kk];
                float4 w1 = *(const float4*)&s_Wb[(half+2)*256 + kk];
                float4 w2 = *(const float4*)&s_Wb[(half+4)*256 + kk];
                float4 w3 = *(const float4*)&s_Wb[(half+6)*256 + kk];
                float4 w4 = *(const float4*)&s_Wb[(half+8)*256 + kk];
                a0 += w0.x*hv0 + w0.y*hv1 + w0.z*hv2 + w0.w*hv3;
                a1 += w1.x*hv0 + w1.y*hv1 + w1.z*hv2 + w1.w*hv3;
                a2 += w2.x*hv0 + w2.y*hv1 + w2.z*hv2 + w2.w*hv3;
                a3 += w3.x*hv0 + w3.y*hv1 + w3.z*hv2 + w3.w*hv3;
                a4 += w4.x*hv0 + w4.y*hv1 + w4.z*hv2 + w4.w*hv3;
            }
            if (kh == 1){
                s_sm[(half+0)*128 + b127] = a0;
                s_sm[(half+2)*128 + b127] = a1;
                s_sm[(half+4)*128 + b127] = a2;
                s_sm[(half+6)*128 + b127] = a3;
                s_sm[(half+8)*128 + b127] = a4;
            }
            __syncthreads();
            if (kh == 0){
                g_hcatT[(size_t)(jj0+half+0)*128 + b127] = a0 + s_sm[(half+0)*128 + b127] + s_bias[half+0];
                g_hcatT[(size_t)(jj0+half+2)*128 + b127] = a1 + s_sm[(half+2)*128 + b127] + s_bias[half+2];
                g_hcatT[(size_t)(jj0+half+4)*128 + b127] = a2 + s_sm[(half+4)*128 + b127] + s_bias[half+4];
                g_hcatT[(size_t)(jj0+half+6)*128 + b127] = a3 + s_sm[(half+6)*128 + b127] + s_bias[half+6];
                g_hcatT[(size_t)(jj0+half+8)*128 + b127] = a4 + s_sm[(half+8)*128 + b127] + s_bias[half+8];
            }
        }
        grid_barrier(++bt);
        // ---- nll for t = it-1 ----
        if (it >= 1){
            float* lg  = s_sm;
            float* red = s_sm + 192;
            float lv = -1e30f;
            if (tid < NC){ lv = g_hcatT[(size_t)(1024+tid)*128 + bsel]; lg[tid] = lv; }
            if (tid < 256) red[tid] = lv;
            __syncthreads();
            for (int s = 128; s; s >>= 1){ if (tid < s) red[tid] = fmaxf(red[tid], red[tid+s]); __syncthreads(); }
            float mx = red[0]; __syncthreads();
            if (tid < 256) red[tid] = (tid < NC) ? __expf(lg[tid] - mx) : 0.f;
            __syncthreads();
            for (int s = 128; s; s >>= 1){ if (tid < s) red[tid] += red[tid+s]; __syncthreads(); }
            if (tid == 0){
                float lse = mx + logf(red[0]);
                int tgt = word_t[bsel*TLEN + (it-1)];
                float v = 0.f;
                if (tgt >= 0){
                    int tc = tgt > (NC-1) ? (NC-1) : tgt;
                    v = lse - lg[tc];
                }
                g_nll[(it-1)*BATCH + bsel] = v;
            }
            __syncthreads();
        }
        if (it == TLEN) break;
        // ---- P2: attention ----
        {
            float* hp  = s_sm + 448;
            float* sc  = s_sm + 704;
            float* red = s_sm + 960;
            if (tid < 256) hp[tid] = g_hcatT[(size_t)tid*128 + bsel];
            __syncthreads();
            if (tid < 128) s_hph[tid] = pkhf(hp[2*tid], hp[2*tid+1]);
            __syncthreads();
            const unsigned* pb = g_preh + (size_t)bsel*LPOS*128;
            for (int l = warp; l < LPOS; l += 32){
                const unsigned* p1 = pb + (size_t)l*128;
                const unsigned* p2 = p1 + 16*128;
                float s1 = 0.f, s2 = 0.f;
                #pragma unroll
                for (int i = 0; i < 4; i++){
                    int p = lane + 32*i;
                    unsigned hv = s_hph[p];
                    unsigned t1 = tanh2u(hadd2u(p1[p], hv));
                    unsigned t2 = tanh2u(hadd2u(p2[p], hv));
                    float2 f1 = uph(t1);
                    float2 f2 = uph(t2);
                    float2 vp = *(const float2*)&s_vv[2*p];
                    s1 += vp.x*f1.x + vp.y*f1.y;
                    s2 += vp.x*f2.x + vp.y*f2.y;
                }
                s1 = warp_sum(s1);
                s2 = warp_sum(s2);
                if (lane == 0){ sc[l] = s1; sc[l+16] = s2; }
            }
            __syncthreads();
            if (tid < 256) red[tid] = sc[tid];
            __syncthreads();
            for (int s = 128; s; s >>= 1){ if (tid < s) red[tid] = fmaxf(red[tid], red[tid+s]); __syncthreads(); }
            float mx = red[0]; __syncthreads();
            float e = 0.f;
            if (tid < 256){ e = __expf(sc[tid] - mx); red[tid] = e; }
            __syncthreads();
            for (int s = 128; s; s >>= 1){ if (tid < s) red[tid] += red[tid+s]; __syncthreads(); }
            float inv = 1.f / red[0]; __syncthreads();
            if (tid < 256) sc[tid] = e * inv;
            __syncthreads();
            // ctx: 16-way warp split over l, f16x2 enc
            {
                float2 part[5];
                #pragma unroll
                for (int i = 0; i < 5; i++){ part[i].x = 0.f; part[i].y = 0.f; }
                const unsigned* eb = g_ench + (size_t)bsel*LPOS*CPAIR;
                int lbase = warp*16;
                for (int ll = 0; ll < 16; ll++){
                    int l = lbase + ll;
                    float wl = sc[l];
                    const unsigned* er = eb + (size_t)l*CPAIR;
                    #pragma unroll
                    for (int i = 0; i < 4; i++){
                        float2 v = uph(er[lane + 32*i]);
                        part[i].x += wl*v.x;
                        part[i].y += wl*v.y;
                    }
                    if (lane < 20){
                        float2 v = uph(er[128 + lane]);
                        part[4].x += wl*v.x;
                        part[4].y += wl*v.y;
                    }
                }
                float* pp = s_sm + 1216;   // 16 x 296
                #pragma unroll
                for (int i = 0; i < 4; i++){
                    int c = 2*(lane + 32*i);
                    pp[warp*CENC + c]     = part[i].x;
                    pp[warp*CENC + c + 1] = part[i].y;
                }
                if (lane < 20){
                    int c = 256 + 2*lane;
                    pp[warp*CENC + c]     = part[4].x;
                    pp[warp*CENC + c + 1] = part[4].y;
                }
                __syncthreads();
                for (int c = tid; c < CENC; c += 512){
                    float a = 0.f;
                    #pragma unroll
                    for (int wq = 0; wq < 16; wq++) a += pp[wq*CENC + c];
                    g_ctxT[(size_t)c*128 + bsel] = a;
                }
            }
        }
        grid_barrier(++bt);
        // ---- P3: gi + gates -> h (c-range split across kh, direct coalesced loads) ----
        {
            float ar = 0.f, az = 0.f, an = 0.f;
            int cbase = kh*CPAIR;
            const float* wr = s_Ws + (half*3+0)*CENC + cbase;
            const float* wz = s_Ws + (half*3+1)*CENC + cbase;
            const float* wn = s_Ws + (half*3+2)*CENC + cbase;
            const float* ctxc = g_ctxT + (size_t)cbase*128 + b127;
            #pragma unroll 4
            for (int i = 0; i < CPAIR; i++){
                float cv = ctxc[(size_t)i*128];
                ar += wr[i]*cv;
                az += wz[i]*cv;
                an += wn[i]*cv;
            }
            if (kh == 1){
                int t2 = tid & 255;
                s_sm[t2] = ar;
                s_sm[256 + t2] = az;
                s_sm[512 + t2] = an;
            }
            __syncthreads();
            if (kh == 0){
                ar += s_sm[tid];
                az += s_sm[256 + tid];
                an += s_sm[512 + tid];
                int hh = hh0 + half;
                const float* giw = g_giw + (size_t)it*768*128;
                float gir = giw[(size_t)(      hh)*128 + b127] + ar;
                float giz = giw[(size_t)(256 + hh)*128 + b127] + az;
                float gin = giw[(size_t)(512 + hh)*128 + b127] + an;
                float ghr = g_hcatT[(size_t)(256 +       hh)*128 + b127];
                float ghz = g_hcatT[(size_t)(256 + 256 + hh)*128 + b127];
                float ghn = g_hcatT[(size_t)(256 + 512 + hh)*128 + b127];
                float r = 1.f/(1.f + __expf(-(gir + ghr)));
                float z = 1.f/(1.f + __expf(-(giz + ghz)));
                float n = tanhf(gin + r*ghn);
                float ho = g_hT[hh*128 + b127];
                g_hT[hh*128 + b127] = (1.f - z)*n + z*ho;
            }
        }
        grid_barrier(++bt);
    }
    grid_barrier(++bt);
    if (cta == 0){
        float* red = s_sm;
        float s = 0.f;
        for (int i = tid; i < TLEN*BATCH; i += 512) s += g_nll[i];
        red[tid] = s; __syncthreads();
        for (int k = 256; k; k >>= 1){ if (tid < k) red[tid] += red[tid+k]; __syncthreads(); }
        if (tid == 0) out[0] = 0.2f * red[0] / (float)BATCH;
    }
}

// ---------------- host ----------------
extern "C" void kernel_launch(void* const* d_in, const int* in_sizes, int n_in,
                              void* d_out, int out_size){
    const float* x        = (const float*)d_in[0];
    const int*   dec_t    = (const int*)  d_in[1];
    const int*   word_t   = (const int*)  d_in[2];
    const float* conv_w   = (const float*)d_in[3];
    const float* conv_b   = (const float*)d_in[4];
    const float* emb_dec  = (const float*)d_in[5];
    const float* word_w   = (const float*)d_in[6];
    const float* word_b   = (const float*)d_in[7];
    const float* attn_w   = (const float*)d_in[8];
    const float* attn_b   = (const float*)d_in[9];
    const float* attn_v   = (const float*)d_in[10];
    const float* gru_wih  = (const float*)d_in[11];
    const float* gru_bih  = (const float*)d_in[12];
    const float* gru_whh  = (const float*)d_in[13];
    const float* gru_bhh  = (const float*)d_in[14];
    const float* out_w    = (const float*)d_in[15];
    const float* out_b    = (const float*)d_in[16];
    const float* x_emb    = (const float*)d_in[17];
    const float* y_emb    = (const float*)d_in[18];
    float* out = (float*)d_out;

    // launch 1: prep (resize + weight packs + zero h)
    prep_kernel<<<RES_BLKS + WRB_BLKS + WC_BLKS + ZH_BLKS, 256>>>(
        x, conv_w, gru_wih, gru_bih, word_w, word_b);
    // launch 2: conv (bf16 MMA) + pool + relu + pos (fp32 + f16x2 enc)
    conv_mma_kernel<<<dim3(BATCH, 8), 512>>>(conv_b, x_emb, y_emb);
    // launch 3: giw GEMM + pre GEMM fused
    mid_kernel<<<GIW_BLKS + PRE_BLKS, 256>>>(emb_dec, dec_t, attn_w, attn_b);
    // launch 4 (profiled): persistent decoder
    decoder_kernel<<<BATCH, 512>>>(attn_v, attn_w, gru_whh, gru_bhh, gru_wih,
                                   out_w, out_b, word_t, out);
    (void)in_sizes; (void)n_in; (void)out_size;
}

// round 17
// speedup vs baseline: 1.1049x; 1.0587x over previous
#include <cuda_runtime.h>
#include <cuda_bf16.h>
#include <cuda_fp16.h>
#include <math.h>

// ---------------- Problem constants ----------------
#define BATCH   128
#define CIN     256
#define HIN     8
#define WIN     32
#define RH      16
#define RW      64
#define HF      8
#define WF      32
#define LPOS    256
#define XOH     32
#define YOH     8
#define CENC    296
#define HID     256
#define NC      163
#define TLEN    32

#define PADH    18
#define PADW    66
#define CPAIR   148     // CENC/2

// ---------------- Scratch ----------------
__device__ float    g_resT[BATCH*PADH*PADW*CIN];
__device__ unsigned g_wrb [9*128*256];
__device__ float    g_wc  [768*NC];
__device__ float    g_bc  [768];
__device__ float    g_enc [BATCH*LPOS*CENC];
__device__ unsigned g_ench[BATCH*LPOS*CPAIR];
__device__ unsigned g_preh[BATCH*LPOS*128];
__device__ float    g_giw[TLEN*768*BATCH];
__device__ unsigned g_hTh  [128*BATCH];           // h as f16x2 [kpair][b]
__device__ float    g_hcatT[1280*BATCH];
__device__ unsigned g_ctxh [CPAIR*BATCH];         // ctx as f16x2 [cpair][b]
__device__ float    g_nll  [TLEN*BATCH];
__device__ unsigned g_bar_arrive;
__device__ unsigned g_bar_epoch;

// ---------------- helpers ----------------
__device__ __forceinline__ float warp_sum(float v){
    #pragma unroll
    for (int o = 16; o; o >>= 1) v += __shfl_down_sync(0xffffffffu, v, o);
    return v;
}
__device__ __forceinline__ float tf32r(float f){
    unsigned u; asm("cvt.rna.tf32.f32 %0, %1;" : "=r"(u) : "f"(f));
    return __uint_as_float(u);
}
__device__ __forceinline__ unsigned pkbf(float a, float b){
    __nv_bfloat162 h = __floats2bfloat162_rn(a, b);
    return *(unsigned*)&h;
}
__device__ __forceinline__ unsigned pkhf(float a, float b){
    __half2 h = __floats2half2_rn(a, b);
    return *(unsigned*)&h;
}
__device__ __forceinline__ unsigned hadd2u(unsigned a, unsigned b){
    unsigned r; asm("add.f16x2 %0, %1, %2;" : "=r"(r) : "r"(a), "r"(b)); return r;
}
__device__ __forceinline__ unsigned tanh2u(unsigned a){
    unsigned r; asm("tanh.approx.f16x2 %0, %1;" : "=r"(r) : "r"(a)); return r;
}
__device__ __forceinline__ float2 uph(unsigned u){
    return __half22float2(*(__half2*)&u);
}
__device__ __forceinline__ void mma_tf32(float* c, const unsigned* a, unsigned b0, unsigned b1){
    asm volatile("mma.sync.aligned.m16n8k8.row.col.f32.tf32.tf32.f32 "
        "{%0,%1,%2,%3}, {%4,%5,%6,%7}, {%8,%9}, {%0,%1,%2,%3};"
        : "+f"(c[0]), "+f"(c[1]), "+f"(c[2]), "+f"(c[3])
        : "r"(a[0]), "r"(a[1]), "r"(a[2]), "r"(a[3]), "r"(b0), "r"(b1));
}
__device__ __forceinline__ void mma_bf16(float* c, const unsigned* a, unsigned b0, unsigned b1){
    asm volatile("mma.sync.aligned.m16n8k16.row.col.f32.bf16.bf16.f32 "
        "{%0,%1,%2,%3}, {%4,%5,%6,%7}, {%8,%9}, {%0,%1,%2,%3};"
        : "+f"(c[0]), "+f"(c[1]), "+f"(c[2]), "+f"(c[3])
        : "r"(a[0]), "r"(a[1]), "r"(a[2]), "r"(a[3]), "r"(b0), "r"(b1));
}
__device__ __forceinline__ unsigned ld_acq(unsigned* p){
    unsigned v; asm volatile("ld.acquire.gpu.u32 %0, [%1];" : "=r"(v) : "l"(p)); return v;
}
__device__ __forceinline__ void grid_barrier(unsigned target){
    __syncthreads();
    if (threadIdx.x == 0){
        unsigned t;
        asm volatile("atom.acq_rel.gpu.global.add.u32 %0, [%1], 1;"
                     : "=r"(t) : "l"(&g_bar_arrive) : "memory");
        if (t == gridDim.x - 1){
            g_bar_arrive = 0u;
            asm volatile("red.release.gpu.global.add.u32 [%0], 1;" :: "l"(&g_bar_epoch) : "memory");
        } else {
            while ((int)(ld_acq(&g_bar_epoch) - target) < 0) __nanosleep(32);
        }
    }
    __syncthreads();
}

// ---------------- K1: fused prep ----------------
#define RES_BLKS  (8*PADH*BATCH)
#define WRB_BLKS  ((9*128*256)/256)
#define WC_BLKS   (768/4)
#define ZH_BLKS   ((128*BATCH)/256)    // zero g_hTh
__global__ __launch_bounds__(256) void prep_kernel(
    const float* __restrict__ x, const float* __restrict__ conv_w,
    const float* __restrict__ wih, const float* __restrict__ bih,
    const float* __restrict__ word_w, const float* __restrict__ word_b)
{
    __shared__ float smem_u[32*67];
    int bid = blockIdx.x;
    int t = threadIdx.x;
    if (bid < RES_BLKS){
        float (*tile)[67] = (float(*)[67])smem_u;
        int cg = bid % 8;
        int yp = (bid / 8) % PADH;
        int b  = bid / (8*PADH);
        int xo  = t & 63;
        int cl0 = (t >> 6)*8;
        bool interior = (yp >= 1 && yp <= 16);
        int y0c = 0, y1c = 0; float fy = 0.f;
        if (interior){
            float sy = 0.5f*(yp-1) - 0.25f;
            int y0 = (int)floorf(sy); fy = sy - (float)y0;
            y0c = y0 < 0 ? 0 : y0;
            y1c = (y0+1) > (HIN-1) ? (HIN-1) : (y0+1);
        }
        float sx = 0.5f*xo - 0.25f;
        int x0 = (int)floorf(sx); float fx = sx - (float)x0;
        int x0c = x0 < 0 ? 0 : x0;
        int x1c = (x0+1) > (WIN-1) ? (WIN-1) : (x0+1);
        #pragma unroll
        for (int i = 0; i < 8; i++){
            int cl = cl0 + i;
            float v = 0.f;
            if (interior){
                const float* base = x + (size_t)(b*CIN + cg*32 + cl)*(HIN*WIN);
                float v00 = base[y0c*WIN + x0c], v01 = base[y0c*WIN + x1c];
                float v10 = base[y1c*WIN + x0c], v11 = base[y1c*WIN + x1c];
                v = (1.f-fy)*((1.f-fx)*v00 + fx*v01) + fy*((1.f-fx)*v10 + fx*v11);
            }
            tile[cl][xo+1] = v;
        }
        if (t < 32){ tile[t][0] = 0.f; tile[t][65] = 0.f; }
        __syncthreads();
        int warp = t >> 5, lane = t & 31;
        for (int xp = warp; xp < PADW; xp += 8){
            g_resT[(((size_t)b*PADH + yp)*PADW + xp)*CIN + cg*32 + lane] = tile[lane][xp];
        }
    } else if (bid < RES_BLKS + WRB_BLKS){
        int idx = (bid - RES_BLKS)*256 + t;
        int o  = idx & 255;
        int kp = (idx >> 8) & 127;
        int s  = idx >> 15;
        float f0 = conv_w[((size_t)o*CIN + 2*kp  )*9 + s];
        float f1 = conv_w[((size_t)o*CIN + 2*kp+1)*9 + s];
        g_wrb[idx] = pkbf(f0, f1);
    } else if (bid < RES_BLKS + WRB_BLKS + WC_BLKS){
        int j0 = (bid - RES_BLKS - WRB_BLKS)*4;
        float* s_wih = smem_u;
        for (int idx = t; idx < 1024; idx += 256){
            int r = idx >> 8, k = idx & 255;
            s_wih[idx] = wih[(size_t)(j0+r)*552 + k];
        }
        __syncthreads();
        if (t < NC){
            float a0=0.f, a1=0.f, a2=0.f, a3=0.f;
            for (int k = 0; k < 256; k++){
                float wv = word_w[k*NC + t];
                a0 += s_wih[      k]*wv;
                a1 += s_wih[256 + k]*wv;
                a2 += s_wih[512 + k]*wv;
                a3 += s_wih[768 + k]*wv;
            }
            g_wc[(size_t)(j0+0)*NC + t] = a0;
            g_wc[(size_t)(j0+1)*NC + t] = a1;
            g_wc[(size_t)(j0+2)*NC + t] = a2;
            g_wc[(size_t)(j0+3)*NC + t] = a3;
        }
        if (t < 4){
            float s = bih[j0 + t];
            for (int k = 0; k < 256; k++) s += s_wih[t*256 + k]*word_b[k];
            g_bc[j0 + t] = s;
        }
    } else {
        int idx = (bid - RES_BLKS - WRB_BLKS - WC_BLKS)*256 + t;
        g_hTh[idx] = 0u;
    }
}

// ---------------- K2: conv3x3 bf16 MMA, double-buffered B ----------------
#define ASTR 12
#define BSTR 12
#define AS_U (4*66*ASTR)
#define BS2_U (2*64*BSTR)
#define SMU_SZ (AS_U + 4*BS2_U)
__global__ __launch_bounds__(512, 1) void conv_mma_kernel(const float* __restrict__ conv_b,
                                                          const float* __restrict__ x_emb,
                                                          const float* __restrict__ y_emb){
    __shared__ __align__(16) unsigned smu[SMU_SZ];
    unsigned* As = smu;
    unsigned* Bs = smu + AS_U;
    int b = blockIdx.x, ytile = blockIdx.y;
    int y0 = ytile*2;
    int tid = threadIdx.x;
    int w = tid >> 5, lane = tid & 31;
    int wm = w & 3, g = w >> 2;
    int quad = lane >> 2, qk = lane & 3;
    int gtid = tid & 127;
    unsigned* BgBuf = Bs + g*BS2_U;
    int yy = wm >> 1;
    int x0 = (wm & 1) << 5;
    int kp2 = gtid >> 6, oo = gtid & 63;

    float acc[2][8][4];
    #pragma unroll
    for (int i=0;i<2;i++)
        #pragma unroll
        for (int j=0;j<8;j++){ acc[i][j][0]=0.f; acc[i][j][1]=0.f; acc[i][j][2]=0.f; acc[i][j][3]=0.f; }

    const float* srcA = g_resT + (size_t)(b*PADH + y0) * (PADW*CIN);
    for (int chunk = 0; chunk < 16; chunk++){
        int c0 = chunk*16;
        __syncthreads();
        for (int e4 = tid; e4 < 4*66*4; e4 += 512){
            int c4 = e4 & 3;
            int xr = (e4 >> 2) % 66;
            int r  = e4 / 264;
            float4 v = *(const float4*)(srcA + ((size_t)r*PADW + xr)*CIN + c0 + c4*4);
            unsigned* d = As + (r*66 + xr)*ASTR + c4*2;
            d[0] = pkbf(v.x, v.y);
            d[1] = pkbf(v.z, v.w);
        }
        __syncthreads();
        {
            const unsigned* src = g_wrb + ((size_t)(chunk*8))*256 + g*64 + oo;
            unsigned* dst = BgBuf;
            #pragma unroll
            for (int kq = 0; kq < 4; kq++){
                int kp = kp2 + kq*2;
                dst[oo*BSTR + kp] = src[(size_t)kp*256];
            }
        }
        asm volatile("bar.sync %0, 128;" :: "r"(g+1));
        for (int s = 0; s < 9; s++){
            if (s < 8){
                const unsigned* src = g_wrb + ((size_t)((s+1)*128 + chunk*8))*256 + g*64 + oo;
                unsigned* dst = BgBuf + ((s+1)&1)*768;
                #pragma unroll
                for (int kq = 0; kq < 4; kq++){
                    int kp = kp2 + kq*2;
                    dst[oo*BSTR + kp] = src[(size_t)kp*256];
                }
            }
            const unsigned* Bg = BgBuf + (s&1)*768;
            int dy = s/3, dx = s - dy*3;
            const unsigned* Abase = As + ((yy+dy)*66 + dx)*ASTR + qk;
            unsigned a[2][4];
            #pragma unroll
            for (int mt = 0; mt < 2; mt++){
                const unsigned* Ap = Abase + (x0 + mt*16 + quad)*ASTR;
                a[mt][0] = Ap[0];
                a[mt][2] = Ap[4];
                a[mt][1] = Ap[8*ASTR];
                a[mt][3] = Ap[8*ASTR + 4];
            }
            #pragma unroll
            for (int nt = 0; nt < 8; nt++){
                const unsigned* Bp = Bg + (nt*8 + quad)*BSTR + qk;
                unsigned b0 = Bp[0];
                unsigned b1 = Bp[4];
                mma_bf16(acc[0][nt], a[0], b0, b1);
                mma_bf16(acc[1][nt], a[1], b0, b1);
            }
            asm volatile("bar.sync %0, 128;" :: "r"(g+1));
        }
    }
    __syncthreads();
    float* epi = (float*)smu + g*(128*17);
    int py = ytile;
    #pragma unroll
    for (int nq = 0; nq < 4; nq++){
        #pragma unroll
        for (int mt = 0; mt < 2; mt++){
            int row0 = wm*32 + mt*16 + quad;
            #pragma unroll
            for (int j = 0; j < 2; j++){
                int nt = nq*2 + j;
                int nn = j*8 + qk*2;
                epi[ row0   *17 + nn]   = acc[mt][nt][0];
                epi[ row0   *17 + nn+1] = acc[mt][nt][1];
                epi[(row0+8)*17 + nn]   = acc[mt][nt][2];
                epi[(row0+8)*17 + nn+1] = acc[mt][nt][3];
            }
        }
        asm volatile("bar.sync %0, 128;" :: "r"(g+1));
        for (int e = gtid; e < 256; e += 128){
            int px = e >> 3, pc = e & 7;
            int m0 = px*2;
            int oc0 = 2*pc;
            float v0 = fmaxf(fmaxf(epi[ m0   *17 + oc0], epi[(m0+1 )*17 + oc0]),
                             fmaxf(epi[(m0+64)*17 + oc0], epi[(m0+65)*17 + oc0]));
            float v1 = fmaxf(fmaxf(epi[ m0   *17 + oc0+1], epi[(m0+1 )*17 + oc0+1]),
                             fmaxf(epi[(m0+64)*17 + oc0+1], epi[(m0+65)*17 + oc0+1]));
            int och0 = g*64 + nq*16 + oc0;
            float r0 = fmaxf(v0 + conv_b[och0],   0.f);
            float r1 = fmaxf(v1 + conv_b[och0+1], 0.f);
            size_t lidx = (size_t)b*LPOS + py*WF + px;
            *(float2*)&g_enc[lidx*CENC + och0] = make_float2(r0, r1);
            g_ench[lidx*CPAIR + (och0 >> 1)] = pkhf(r0, r1);
        }
        asm volatile("bar.sync %0, 128;" :: "r"(g+1));
    }
    for (int e = tid; e < WF*20; e += 512){
        int px = e / 20, pq = e % 20;
        int c0 = 2*pq;
        float v0, v1;
        if (c0 < 32){ v0 = x_emb[px*XOH + c0]; v1 = x_emb[px*XOH + c0+1]; }
        else        { v0 = y_emb[py*YOH + (c0-32)]; v1 = y_emb[py*YOH + (c0-31)]; }
        size_t lidx = (size_t)b*LPOS + py*WF + px;
        *(float2*)&g_enc[lidx*CENC + 256 + c0] = make_float2(v0, v1);
        g_ench[lidx*CPAIR + 128 + pq] = pkhf(v0, v1);
    }
}

// ---------------- K3: mid kernel = giw gather GEMM + pre tf32 GEMM ----------------
#define BM 64
#define BN 64
#define BK 16
#define GM 128
#define GN 64
#define GAPAD 20
#define GBPAD 20
#define GIW_BLKS 768
#define PRE_BLKS 1024
__global__ __launch_bounds__(256) void mid_kernel(
    const float* __restrict__ emb, const int* __restrict__ dec_t,
    const float* __restrict__ attn_w, const float* __restrict__ attn_b)
{
    __shared__ __align__(16) float smid[3840];
    int bid = blockIdx.x;
    int tid = threadIdx.x;
    if (bid < GIW_BLKS){
        float* As = smid;
        float* Bs = smid + 1088;
        const int M = TLEN*BATCH, K = NC;
        int m0 = (bid & 63) * BM, n0 = (bid >> 6) * BN;
        int ty = tid >> 4, tx = tid & 15;
        float acc[4][4];
        #pragma unroll
        for (int i=0;i<4;i++){ acc[i][0]=0.f; acc[i][1]=0.f; acc[i][2]=0.f; acc[i][3]=0.f; }
        for (int k0 = 0; k0 < K; k0 += BK){
            #pragma unroll
            for (int e = tid; e < BM*BK; e += 256){
                int ml = e >> 4, kk = e & 15;
                int m = m0 + ml, k = k0 + kk;
                float v = 0.f;
                if (m < M && k < K){
                    int tt = m >> 7, bb = m & 127;
                    int row = (tt == 0) ? 0 : dec_t[bb*TLEN + (tt-1)];
                    v = emb[(size_t)row*NC + k];
                }
                As[kk*68 + ml] = v;
            }
            #pragma unroll
            for (int e = tid; e < BN*BK; e += 256){
                int nl = e >> 4, kk = e & 15;
                int n = n0 + nl, k = k0 + kk;
                float v = 0.f;
                if (k < K) v = g_wc[(size_t)n*NC + k];
                Bs[kk*68 + nl] = v;
            }
            __syncthreads();
            #pragma unroll
            for (int kk = 0; kk < BK; kk++){
                float4 a = *(const float4*)&As[kk*68 + ty*4];
                float4 bb = *(const float4*)&Bs[kk*68 + tx*4];
                float av[4] = {a.x, a.y, a.z, a.w};
                float bv[4] = {bb.x, bb.y, bb.z, bb.w};
                #pragma unroll
                for (int i=0;i<4;i++)
                    #pragma unroll
                    for (int j=0;j<4;j++) acc[i][j] += av[i]*bv[j];
            }
            __syncthreads();
        }
        #pragma unroll
        for (int i=0;i<4;i++){
            int m = m0 + ty*4 + i;
            #pragma unroll
            for (int j=0;j<4;j++){
                int n = n0 + tx*4 + j;
                g_giw[((size_t)(m>>7)*768 + n)*128 + (m&127)] = acc[i][j] + g_bc[n];
            }
        }
    } else {
        float* As = smid;
        float* Bs = smid + 2560;
        int idx = bid - GIW_BLKS;
        int m0 = (idx & 255) * GM, n0 = (idx >> 8) * GN;
        const float* A = g_enc;
        const float* B = attn_w + 256;
        const int lda = CENC, ldb = 552, K = CENC;
        int w = tid>>5, lane = tid&31;
        int wm = w & 3, wn = w >> 2;
        int quad = lane >> 2, qk = lane & 3;
        float acc[2][4][4];
        #pragma unroll
        for (int i=0;i<2;i++)
            #pragma unroll
            for (int j=0;j<4;j++){ acc[i][j][0]=0.f; acc[i][j][1]=0.f; acc[i][j][2]=0.f; acc[i][j][3]=0.f; }
        int nk = (K + 15)/16;
        for (int ki = 0; ki < nk; ki++){
            int k0 = ki*16;
            __syncthreads();
            #pragma unroll
            for (int j = 0; j < 2; j++){
                int i2 = tid + j*256;
                int row = i2 >> 2, kq = i2 & 3;
                int k = k0 + kq*4;
                const float* ap = A + (size_t)(m0+row)*lda + k;
                float4 v;
                if (k + 3 < K) v = *(const float4*)ap;
                else {
                    v.x = (k   < K) ? ap[0] : 0.f;
                    v.y = (k+1 < K) ? ap[1] : 0.f;
                    v.z = (k+2 < K) ? ap[2] : 0.f;
                    v.w = (k+3 < K) ? ap[3] : 0.f;
                }
                float* d = As + row*GAPAD + kq*4;
                d[0]=tf32r(v.x); d[1]=tf32r(v.y); d[2]=tf32r(v.z); d[3]=tf32r(v.w);
            }
            {
                int row = tid >> 2, kq = tid & 3;
                int k = k0 + kq*4;
                const float* bp = B + (size_t)(n0+row)*ldb + k;
                float4 v;
                if (k + 3 < K) v = *(const float4*)bp;
                else {
                    v.x = (k   < K) ? bp[0] : 0.f;
                    v.y = (k+1 < K) ? bp[1] : 0.f;
                    v.z = (k+2 < K) ? bp[2] : 0.f;
                    v.w = (k+3 < K) ? bp[3] : 0.f;
                }
                float* d = Bs + row*GBPAD + kq*4;
                d[0]=tf32r(v.x); d[1]=tf32r(v.y); d[2]=tf32r(v.z); d[3]=tf32r(v.w);
            }
            __syncthreads();
            #pragma unroll
            for (int k8 = 0; k8 < 2; k8++){
                unsigned a[2][4];
                #pragma unroll
                for (int mf = 0; mf < 2; mf++){
                    const float* Ap = As + (wm*32 + mf*16 + quad)*GAPAD + k8*8 + qk;
                    a[mf][0] = __float_as_uint(Ap[0]);
                    a[mf][2] = __float_as_uint(Ap[4]);
                    a[mf][1] = __float_as_uint(Ap[8*GAPAD]);
                    a[mf][3] = __float_as_uint(Ap[8*GAPAD+4]);
                }
                #pragma unroll
                for (int nf = 0; nf < 4; nf++){
                    const float* Bp = Bs + (wn*32 + nf*8 + quad)*GBPAD + k8*8 + qk;
                    unsigned b0 = __float_as_uint(Bp[0]);
                    unsigned b1 = __float_as_uint(Bp[4]);
                    mma_tf32(acc[0][nf], a[0], b0, b1);
                    mma_tf32(acc[1][nf], a[1], b0, b1);
                }
            }
        }
        #pragma unroll
        for (int mf = 0; mf < 2; mf++){
            #pragma unroll
            for (int nf = 0; nf < 4; nf++){
                int m = m0 + wm*32 + mf*16 + quad;
                int n = n0 + wn*32 + nf*8 + qk*2;
                float bi0 = attn_b[n], bi1 = attn_b[n+1];
                g_preh[(size_t)m*128 + (n>>1)]     = pkhf(acc[mf][nf][0] + bi0, acc[mf][nf][1] + bi1);
                g_preh[(size_t)(m+8)*128 + (n>>1)] = pkhf(acc[mf][nf][2] + bi0, acc[mf][nf][3] + bi1);
            }
        }
    }
}

// ---------------- K4: persistent decoder (512 threads) ----------------
__global__ __launch_bounds__(512) void decoder_kernel(
    const float* __restrict__ attn_v, const float* __restrict__ attn_w,
    const float* __restrict__ whh, const float* __restrict__ bhh,
    const float* __restrict__ wih, const float* __restrict__ out_w,
    const float* __restrict__ out_b, const int* __restrict__ word_t,
    float* __restrict__ out)
{
    __shared__ __align__(16) float s_Wb[2560];
    __shared__ __align__(16) float s_Ws[6*CENC];
    __shared__ float s_bias[12];
    __shared__ __align__(16) float s_vv[256];
    __shared__ __align__(16) unsigned s_hph[128];
    __shared__ __align__(16) float s_sm[6144];
    __shared__ unsigned s_ep;

    int cta = blockIdx.x, tid = threadIdx.x;
    int b127 = tid & 127;
    int kh   = tid >> 8;
    int half = (tid >> 7) & 1;
    int jj0 = cta*10;
    int bsel = cta;
    int hh0 = cta*2;
    int warp = tid >> 5, lane = tid & 31;

    for (int idx = tid; idx < 2560; idx += 512){
        int r = idx >> 8, k = idx & 255;
        int j = jj0 + r;
        float v = 0.f;
        if (j < 256)        v = attn_w[j*552 + k];
        else if (j < 1024)  v = whh[(j-256)*256 + k];
        else if (j < 1187)  v = out_w[(j-1024)*256 + k];
        s_Wb[r*256 + k] = v;
    }
    if (tid < 10){
        int j = jj0 + tid;
        float v = 0.f;
        if (j >= 256 && j < 1024)       v = bhh[j-256];
        else if (j >= 1024 && j < 1187) v = out_b[j-1024];
        s_bias[tid] = v;
    }
    for (int idx = tid; idx < 6*CENC; idx += 512){
        int r = idx / CENC, c = idx - r*CENC;
        int rhalf = r / 3, gate = r - rhalf*3;
        int j = gate*256 + hh0 + rhalf;
        s_Ws[idx] = wih[j*552 + 256 + c];
    }
    if (tid < 256) s_vv[tid] = attn_v[tid];
    if (tid == 0) s_ep = ld_acq(&g_bar_epoch);
    __syncthreads();
    unsigned bt = s_ep;
    float h_old = 0.f;    // carried h for (hh0+half, b127), valid for kh==0 threads

    for (int it = 0; it <= TLEN; it++){
        // ---- P1: rows jj0..jj0+9, k-split, f16x2 h ----
        {
            float a0=0.f, a1=0.f, a2=0.f, a3=0.f, a4=0.f;
            const unsigned* hcolh = g_hTh + b127;
            int kpb = kh*64;
            #pragma unroll 8
            for (int kp = 0; kp < 64; kp++){
                float2 hv = uph(hcolh[(size_t)(kpb+kp)*128]);
                int kk = (kpb+kp)*2;
                float2 w0 = *(const float2*)&s_Wb[(half+0)*256 + kk];
                float2 w1 = *(const float2*)&s_Wb[(half+2)*256 + kk];
                float2 w2 = *(const float2*)&s_Wb[(half+4)*256 + kk];
                float2 w3 = *(const float2*)&s_Wb[(half+6)*256 + kk];
                float2 w4 = *(const float2*)&s_Wb[(half+8)*256 + kk];
                a0 += w0.x*hv.x + w0.y*hv.y;
                a1 += w1.x*hv.x + w1.y*hv.y;
                a2 += w2.x*hv.x + w2.y*hv.y;
                a3 += w3.x*hv.x + w3.y*hv.y;
                a4 += w4.x*hv.x + w4.y*hv.y;
            }
            if (kh == 1){
                s_sm[(half+0)*128 + b127] = a0;
                s_sm[(half+2)*128 + b127] = a1;
                s_sm[(half+4)*128 + b127] = a2;
                s_sm[(half+6)*128 + b127] = a3;
                s_sm[(half+8)*128 + b127] = a4;
            }
            __syncthreads();
            if (kh == 0){
                g_hcatT[(size_t)(jj0+half+0)*128 + b127] = a0 + s_sm[(half+0)*128 + b127] + s_bias[half+0];
                g_hcatT[(size_t)(jj0+half+2)*128 + b127] = a1 + s_sm[(half+2)*128 + b127] + s_bias[half+2];
                g_hcatT[(size_t)(jj0+half+4)*128 + b127] = a2 + s_sm[(half+4)*128 + b127] + s_bias[half+4];
                g_hcatT[(size_t)(jj0+half+6)*128 + b127] = a3 + s_sm[(half+6)*128 + b127] + s_bias[half+6];
                g_hcatT[(size_t)(jj0+half+8)*128 + b127] = a4 + s_sm[(half+8)*128 + b127] + s_bias[half+8];
            }
        }
        grid_barrier(++bt);
        // ---- region 2: [nll(it-1) on warp 15] || [P2 scores on warps 0..14], then softmax+ctx ----
        if (it < TLEN){
            float* hp = s_sm + 448;
            if (tid < 256) hp[tid] = g_hcatT[(size_t)tid*128 + bsel];
            __syncthreads();
            if (tid < 128) s_hph[tid] = pkhf(hp[2*tid], hp[2*tid+1]);
            __syncthreads();
        }
        if (it >= 1 && warp == 15){
            // nll via intra-warp shuffles only
            float vals[6];
            float mx = -1e30f;
            #pragma unroll
            for (int i = 0; i < 6; i++){
                int j = lane + 32*i;
                vals[i] = (j < NC) ? g_hcatT[(size_t)(1024+j)*128 + bsel] : -1e30f;
                mx = fmaxf(mx, vals[i]);
            }
            #pragma unroll
            for (int o = 16; o; o >>= 1) mx = fmaxf(mx, __shfl_xor_sync(0xffffffffu, mx, o));
            float sm = 0.f;
            #pragma unroll
            for (int i = 0; i < 6; i++){
                int j = lane + 32*i;
                if (j < NC) sm += __expf(vals[i] - mx);
            }
            #pragma unroll
            for (int o = 16; o; o >>= 1) sm += __shfl_xor_sync(0xffffffffu, sm, o);
            if (lane == 0){
                float lse = mx + logf(sm);
                int tgt = word_t[bsel*TLEN + (it-1)];
                float v = 0.f;
                if (tgt >= 0){
                    int tc = tgt > (NC-1) ? (NC-1) : tgt;
                    v = lse - g_hcatT[(size_t)(1024+tc)*128 + bsel];
                }
                g_nll[(it-1)*BATCH + bsel] = v;
            }
        }
        if (it == TLEN) break;
        {
            float* sc  = s_sm + 704;
            float* red = s_sm + 960;
            // scores on warps 0..14 (stride-30 pair coverage)
            if (warp < 15){
                const unsigned* pb = g_preh + (size_t)bsel*LPOS*128;
                for (int l = warp; l < LPOS; l += 30){
                    int l2 = l + 15;
                    bool has2 = (l2 < LPOS);
                    const unsigned* p1 = pb + (size_t)l*128;
                    const unsigned* p2 = pb + (size_t)(has2 ? l2 : l)*128;
                    float s1 = 0.f, s2 = 0.f;
                    #pragma unroll
                    for (int i = 0; i < 4; i++){
                        int p = lane + 32*i;
                        unsigned hv = s_hph[p];
                        unsigned t1 = tanh2u(hadd2u(p1[p], hv));
                        unsigned t2 = tanh2u(hadd2u(p2[p], hv));
                        float2 f1 = uph(t1);
                        float2 f2 = uph(t2);
                        float2 vp = *(const float2*)&s_vv[2*p];
                        s1 += vp.x*f1.x + vp.y*f1.y;
                        s2 += vp.x*f2.x + vp.y*f2.y;
                    }
                    s1 = warp_sum(s1);
                    s2 = warp_sum(s2);
                    if (lane == 0){
                        sc[l] = s1;
                        if (has2) sc[l2] = s2;
                    }
                }
            }
            __syncthreads();
            // softmax: shuffle + 2-level
            float sv = (tid < 256) ? sc[tid] : -1e30f;
            float m = sv;
            #pragma unroll
            for (int o = 16; o; o >>= 1) m = fmaxf(m, __shfl_xor_sync(0xffffffffu, m, o));
            if (lane == 0) red[warp] = m;
            __syncthreads();
            if (warp == 0){
                float mm = (lane < 16) ? red[lane] : -1e30f;
                #pragma unroll
                for (int o = 8; o; o >>= 1) mm = fmaxf(mm, __shfl_xor_sync(0xffffffffu, mm, o));
                if (lane == 0) red[16] = mm;
            }
            __syncthreads();
            float mx = red[16];
            float e = (tid < 256) ? __expf(sv - mx) : 0.f;
            float s = e;
            #pragma unroll
            for (int o = 16; o; o >>= 1) s += __shfl_xor_sync(0xffffffffu, s, o);
            if (lane == 0) red[17 + warp] = s;
            __syncthreads();
            if (warp == 0){
                float ss = (lane < 16) ? red[17 + lane] : 0.f;
                #pragma unroll
                for (int o = 8; o; o >>= 1) ss += __shfl_xor_sync(0xffffffffu, ss, o);
                if (lane == 0) red[33] = 1.f / ss;
            }
            __syncthreads();
            if (tid < 256) sc[tid] = e * red[33];
            __syncthreads();
            // ctx: 16-way warp split over l, f16x2 enc, output f16x2
            {
                float2 part[5];
                #pragma unroll
                for (int i = 0; i < 5; i++){ part[i].x = 0.f; part[i].y = 0.f; }
                const unsigned* eb = g_ench + (size_t)bsel*LPOS*CPAIR;
                int lbase = warp*16;
                for (int ll = 0; ll < 16; ll++){
                    int l = lbase + ll;
                    float wl = sc[l];
                    const unsigned* er = eb + (size_t)l*CPAIR;
                    #pragma unroll
                    for (int i = 0; i < 4; i++){
                        float2 v = uph(er[lane + 32*i]);
                        part[i].x += wl*v.x;
                        part[i].y += wl*v.y;
                    }
                    if (lane < 20){
                        float2 v = uph(er[128 + lane]);
                        part[4].x += wl*v.x;
                        part[4].y += wl*v.y;
                    }
                }
                float* pp = s_sm + 1216;
                #pragma unroll
                for (int i = 0; i < 4; i++){
                    int c = 2*(lane + 32*i);
                    pp[warp*CENC + c]     = part[i].x;
                    pp[warp*CENC + c + 1] = part[i].y;
                }
                if (lane < 20){
                    int c = 256 + 2*lane;
                    pp[warp*CENC + c]     = part[4].x;
                    pp[warp*CENC + c + 1] = part[4].y;
                }
                __syncthreads();
                for (int cp = tid; cp < CPAIR; cp += 512){
                    float a0 = 0.f, a1 = 0.f;
                    #pragma unroll
                    for (int wq = 0; wq < 16; wq++){
                        a0 += pp[wq*CENC + 2*cp];
                        a1 += pp[wq*CENC + 2*cp + 1];
                    }
                    g_ctxh[(size_t)cp*128 + bsel] = pkhf(a0, a1);
                }
            }
        }
        grid_barrier(++bt);
        // ---- P3: gi + gates -> h (pair-split c across kh, prefetched operands) ----
        {
            int hh = hh0 + half;
            float gir = 0.f, giz = 0.f, gin = 0.f, ghr = 0.f, ghz = 0.f, ghn = 0.f;
            if (kh == 0){
                const float* giw = g_giw + (size_t)it*768*128;
                gir = giw[(size_t)(      hh)*128 + b127];
                giz = giw[(size_t)(256 + hh)*128 + b127];
                gin = giw[(size_t)(512 + hh)*128 + b127];
                ghr = g_hcatT[(size_t)(256 +       hh)*128 + b127];
                ghz = g_hcatT[(size_t)(256 + 256 + hh)*128 + b127];
                ghn = g_hcatT[(size_t)(256 + 512 + hh)*128 + b127];
            }
            float ar = 0.f, az = 0.f, an = 0.f;
            int cpb = kh*74;
            const float* wr = s_Ws + (half*3+0)*CENC + cpb*2;
            const float* wz = s_Ws + (half*3+1)*CENC + cpb*2;
            const float* wn = s_Ws + (half*3+2)*CENC + cpb*2;
            const unsigned* ctxc = g_ctxh + (size_t)cpb*128 + b127;
            #pragma unroll 4
            for (int i = 0; i < 74; i++){
                float2 cv = uph(ctxc[(size_t)i*128]);
                float2 wrv = *(const float2*)&wr[2*i];
                float2 wzv = *(const float2*)&wz[2*i];
                float2 wnv = *(const float2*)&wn[2*i];
                ar += wrv.x*cv.x + wrv.y*cv.y;
                az += wzv.x*cv.x + wzv.y*cv.y;
                an += wnv.x*cv.x + wnv.y*cv.y;
            }
            if (kh == 1){
                int t2 = tid & 255;
                s_sm[t2]       = ar;
                s_sm[256 + t2] = az;
                s_sm[512 + t2] = an;
            }
            __syncthreads();
            float h_new = 0.f;
            if (kh == 0){
                ar += s_sm[tid];
                az += s_sm[256 + tid];
                an += s_sm[512 + tid];
                float r = 1.f/(1.f + __expf(-(gir + ar + ghr)));
                float z = 1.f/(1.f + __expf(-(giz + az + ghz)));
                float n = tanhf(gin + an + r*ghn);
                h_new = (1.f - z)*n + z*h_old;
                h_old = h_new;
                if (half == 1) s_sm[768 + b127] = h_new;
            }
            __syncthreads();
            if (kh == 0 && half == 0){
                g_hTh[(size_t)cta*128 + b127] = pkhf(h_new, s_sm[768 + b127]);
            }
        }
        grid_barrier(++bt);
    }
    grid_barrier(++bt);
    if (cta == 0){
        float* red = s_sm;
        float s = 0.f;
        for (int i = tid; i < TLEN*BATCH; i += 512) s += g_nll[i];
        red[tid] = s; __syncthreads();
        for (int k = 256; k; k >>= 1){ if (tid < k) red[tid] += red[tid+k]; __syncthreads(); }
        if (tid == 0) out[0] = 0.2f * red[0] / (float)BATCH;
    }
}

// ---------------- host ----------------
extern "C" void kernel_launch(void* const* d_in, const int* in_sizes, int n_in,
                              void* d_out, int out_size){
    const float* x        = (const float*)d_in[0];
    const int*   dec_t    = (const int*)  d_in[1];
    const int*   word_t   = (const int*)  d_in[2];
    const float* conv_w   = (const float*)d_in[3];
    const float* conv_b   = (const float*)d_in[4];
    const float* emb_dec  = (const float*)d_in[5];
    const float* word_w   = (const float*)d_in[6];
    const float* word_b   = (const float*)d_in[7];
    const float* attn_w   = (const float*)d_in[8];
    const float* attn_b   = (const float*)d_in[9];
    const float* attn_v   = (const float*)d_in[10];
    const float* gru_wih  = (const float*)d_in[11];
    const float* gru_bih  = (const float*)d_in[12];
    const float* gru_whh  = (const float*)d_in[13];
    const float* gru_bhh  = (const float*)d_in[14];
    const float* out_w    = (const float*)d_in[15];
    const float* out_b    = (const float*)d_in[16];
    const float* x_emb    = (const float*)d_in[17];
    const float* y_emb    = (const float*)d_in[18];
    float* out = (float*)d_out;

    prep_kernel<<<RES_BLKS + WRB_BLKS + WC_BLKS + ZH_BLKS, 256>>>(
        x, conv_w, gru_wih, gru_bih, word_w, word_b);
    conv_mma_kernel<<<dim3(BATCH, 8), 512>>>(conv_b, x_emb, y_emb);
    mid_kernel<<<GIW_BLKS + PRE_BLKS, 256>>>(emb_dec, dec_t, attn_w, attn_b);
    decoder_kernel<<<BATCH, 512>>>(attn_v, attn_w, gru_whh, gru_bhh, gru_wih,
                                   out_w, out_b, word_t, out);
    (void)in_sizes; (void)n_in; (void)out_size;
}